// round 15
// baseline (speedup 1.0000x reference)
#include <cuda_runtime.h>
#include <cuda_bf16.h>
#include <cuda_fp16.h>
#include <cfloat>
#include <math.h>
#include <stdint.h>

// ---------------- problem constants ----------------
#define NN 1792
#define DD 4096
#define HH 8
#define DHH 96
#define INNER 768
#define NL 16
#define FF 8192
#define BT 16
#define XROWS 28672
#define LATROWS 256
#define EPS 1e-5f
#define ATTN_SCALE 0.10206207261596577f

// ---------------- scratch ----------------
__device__ float g_mean[XROWS];
__device__ float g_rstd[XROWS];
__device__ int   g_mask_kind;

__device__ float g_ql[NL * DD];
__device__ float g_qp[8 * NL * INNER];

__device__ float g_QTT[DD * 128];
__device__ float g_QG[DD * 128];
__device__ float g_u[128];
__device__ float g_v[128];
__device__ float g_bv[INNER];
__device__ float g_up[16 * 128];
__device__ float g_vp[16 * 128];
__device__ float g_bvp[16 * INNER];

__device__ float g_S0[(size_t)XROWS * 128];
__device__ float g_C[(size_t)BT * 128 * NN];
__device__ float g_s[BT * 128];
__device__ float g_Y[(size_t)HH * LATROWS * DD];

__device__ float g_Vp[8 * (size_t)LATROWS * INNER];
__device__ float g_attnv[LATROWS * INNER];
__device__ float g_woutp[2 * (size_t)LATROWS * DD];
__device__ float g_lat1[LATROWS * DD];
__device__ float g_ffln[LATROWS * DD];
__device__ float g_ff1p[2 * (size_t)LATROWS * FF];
__device__ float g_h1[(size_t)LATROWS * FF];
__device__ float g_ff2p[2 * (size_t)LATROWS * DD];
__device__ float g_lat2[LATROWS * DD];

// ---------------- helpers ----------------
__device__ __forceinline__ uint32_t smem_u32(const void* p) {
    uint32_t a;
    asm("{ .reg .u64 t; cvta.to.shared.u64 t, %1; cvt.u32.u64 %0, t; }" : "=r"(a) : "l"(p));
    return a;
}
__device__ __forceinline__ void ldm_x4(uint32_t* r, uint32_t addr) {
    asm volatile("ldmatrix.sync.aligned.m8n8.x4.shared.b16 {%0,%1,%2,%3}, [%4];"
                 : "=r"(r[0]), "=r"(r[1]), "=r"(r[2]), "=r"(r[3]) : "r"(addr));
}
__device__ __forceinline__ void ldm_x4t(uint32_t* r, uint32_t addr) {
    asm volatile("ldmatrix.sync.aligned.m8n8.x4.trans.shared.b16 {%0,%1,%2,%3}, [%4];"
                 : "=r"(r[0]), "=r"(r[1]), "=r"(r[2]), "=r"(r[3]) : "r"(addr));
}
__device__ __forceinline__ void mma16816(float* c, const uint32_t* a, const uint32_t* b) {
    asm volatile(
        "mma.sync.aligned.m16n8k16.row.col.f32.bf16.bf16.f32 "
        "{%0,%1,%2,%3}, {%4,%5,%6,%7}, {%8,%9}, {%0,%1,%2,%3};"
        : "+f"(c[0]), "+f"(c[1]), "+f"(c[2]), "+f"(c[3])
        : "r"(a[0]), "r"(a[1]), "r"(a[2]), "r"(a[3]), "r"(b[0]), "r"(b[1]));
}
__device__ __forceinline__ void mma16816h(float* c, const uint32_t* a, const uint32_t* b) {
    asm volatile(
        "mma.sync.aligned.m16n8k16.row.col.f32.f16.f16.f32 "
        "{%0,%1,%2,%3}, {%4,%5,%6,%7}, {%8,%9}, {%0,%1,%2,%3};"
        : "+f"(c[0]), "+f"(c[1]), "+f"(c[2]), "+f"(c[3])
        : "r"(a[0]), "r"(a[1]), "r"(a[2]), "r"(a[3]), "r"(b[0]), "r"(b[1]));
}
__device__ __forceinline__ void split2(float x, float y, unsigned& h, unsigned& l) {
    __nv_bfloat162 hh = __floats2bfloat162_rn(x, y);
    float r0 = x - __bfloat162float(__low2bfloat16(hh));
    float r1 = y - __bfloat162float(__high2bfloat16(hh));
    __nv_bfloat162 ll = __floats2bfloat162_rn(r0, r1);
    h = *reinterpret_cast<unsigned*>(&hh);
    l = *reinterpret_cast<unsigned*>(&ll);
}
__device__ __forceinline__ void split2h(float x, float y, unsigned& h, unsigned& l) {
    __half2 hh = __floats2half2_rn(x, y);
    float r0 = x - __half2float(__low2half(hh));
    float r1 = y - __half2float(__high2half(hh));
    __half2 ll = __floats2half2_rn(r0, r1);
    h = *reinterpret_cast<unsigned*>(&hh);
    l = *reinterpret_cast<unsigned*>(&ll);
}
__device__ __forceinline__ unsigned packh(float x, float y) {
    __half2 hh = __floats2half2_rn(x, y);
    return *reinterpret_cast<unsigned*>(&hh);
}
#define STS16(addr, a, b, c, d) \
    asm volatile("st.shared.v4.b32 [%0], {%1,%2,%3,%4};" :: \
        "r"(addr), "r"(a), "r"(b), "r"(c), "r"(d))

// ---------------- mask kind detection ----------------
__global__ void detect_mask_kernel(const unsigned int* __restrict__ m) {
    __shared__ unsigned int sh[8];
    unsigned int orv = 0;
    for (int i = threadIdx.x; i < XROWS / 4; i += 256) orv |= m[i];
    #pragma unroll
    for (int o = 16; o; o >>= 1) orv |= __shfl_xor_sync(0xffffffffu, orv, o);
    int w = threadIdx.x >> 5;
    if ((threadIdx.x & 31) == 0) sh[w] = orv;
    __syncthreads();
    if (threadIdx.x == 0) {
        unsigned int t = 0;
        #pragma unroll
        for (int i = 0; i < 8; i++) t |= sh[i];
        g_mask_kind = (t <= 1u) ? 1 : 0;
    }
}

// ---------------- layernorm ----------------
__global__ void ln_rows_kernel(const float* __restrict__ in, float* __restrict__ out,
                               const float* __restrict__ g, const float* __restrict__ b) {
    int row = blockIdx.x;
    const float* xr = in + (size_t)row * DD;
    float s = 0.f, q = 0.f;
    for (int i = threadIdx.x; i < DD; i += blockDim.x) { float v = xr[i]; s += v; q += v * v; }
    #pragma unroll
    for (int o = 16; o; o >>= 1) {
        s += __shfl_xor_sync(0xffffffffu, s, o);
        q += __shfl_xor_sync(0xffffffffu, q, o);
    }
    __shared__ float sh_s[8], sh_q[8];
    __shared__ float m_sh, r_sh;
    int w = threadIdx.x >> 5, l = threadIdx.x & 31;
    if (l == 0) { sh_s[w] = s; sh_q[w] = q; }
    __syncthreads();
    if (threadIdx.x == 0) {
        float S = 0.f, Q = 0.f;
        #pragma unroll
        for (int i = 0; i < 8; i++) { S += sh_s[i]; Q += sh_q[i]; }
        float m = S / (float)DD;
        m_sh = m;
        r_sh = rsqrtf(Q / (float)DD - m * m + EPS);
    }
    __syncthreads();
    float m = m_sh, r = r_sh;
    for (int i = threadIdx.x; i < DD; i += blockDim.x)
        out[(size_t)row * DD + i] = (xr[i] - m) * r * g[i] + b[i];
}

// ====== GEMM tiles: 128(M) x 64(N), 256 thr, warp tile 32x32, 2 CTAs/SM =====
#define HSTRIDE 40
#define BST2 72          // B smem row stride (bf16), 64 cols + pad
#define A_BUF 5120       // 128*HSTRIDE elems
#define B_BUF2 2304      // 32*BST2 elems
#define HSMEM3 (8 * A_BUF + 8 * B_BUF2)   // bytes = 59392
#define HSMEM2 (8 * A_BUF + 4 * B_BUF2)   // bytes = 50176

// ===== hmma3: bf16 3-term =====
__global__ void __launch_bounds__(256, 2)
hmma3(const float* __restrict__ A, long long lda, long long abatch,
      const float* __restrict__ B, long long ldb, long long bbatch,
      float* __restrict__ Cc, long long ldc, long long cbatch, long long csplit,
      int M, int Nvalid, int Ktot, int nsplit,
      float* __restrict__ stats_mean, float* __restrict__ stats_rstd) {
    extern __shared__ __nv_bfloat16 dynsm[];
    uint32_t dm_u = smem_u32(dynsm);

    int tid = threadIdx.x, wid = tid >> 5, lid = tid & 31;
    int z = blockIdx.z;
    int batch = z / nsplit, split = z - batch * nsplit;
    int n0 = blockIdx.x * 64, m0 = blockIdx.y * 128;
    int Kchunk = Ktot / nsplit, kbeg = split * Kchunk;
    int L = Kchunk / 32;

    const float* Ab = A + abatch * batch;
    const float* Bb = B + bbatch * batch;
    float* Cb = Cc + cbatch * batch + csplit * split;

    int ar = tid >> 1, ac = (tid & 1) * 16;
    bool aok = (m0 + ar) < M;
    const float* ap = Ab + (long long)(m0 + ar) * lda + kbeg + ac;
    int kb = tid >> 3, cb = (tid & 7) * 8;
    const float* bp = Bb + (long long)(kbeg + kb) * ldb + n0 + cb;
    bool bok0 = (n0 + cb) < Nvalid, bok1 = (n0 + cb + 4) < Nvalid;

    int wm = wid >> 1, wn = wid & 1;
    float acc[2][4][4];
    #pragma unroll
    for (int a1 = 0; a1 < 2; a1++)
        #pragma unroll
        for (int b1 = 0; b1 < 4; b1++)
            #pragma unroll
            for (int c1 = 0; c1 < 4; c1++) acc[a1][b1][c1] = 0.f;

    uint32_t a_off = (uint32_t)(((lid & 15)) * HSTRIDE + (lid >> 4) * 8) * 2;
    uint32_t b_off = (uint32_t)(((lid & 15)) * BST2 + ((lid >> 4) << 3)) * 2;
    uint32_t ast = (uint32_t)(ar * HSTRIDE + ac) * 2;
    uint32_t bst = (uint32_t)(kb * BST2 + cb) * 2;

    bool do_stats = (stats_mean != nullptr) && (blockIdx.x == 0);
    float ssum = 0.f, sqsum = 0.f;

    float4 pa0, pa1, pa2, pa3, pb0, pb1;
    {
        float4 zz = make_float4(0.f, 0.f, 0.f, 0.f);
        pa0 = aok ? *(const float4*)(ap)      : zz;
        pa1 = aok ? *(const float4*)(ap + 4)  : zz;
        pa2 = aok ? *(const float4*)(ap + 8)  : zz;
        pa3 = aok ? *(const float4*)(ap + 12) : zz;
        pb0 = bok0 ? *(const float4*)(bp)     : zz;
        pb1 = bok1 ? *(const float4*)(bp + 4) : zz;
    }

    for (int cc = 0; cc < L; cc++) {
        int s = cc & 1;
        uint32_t aHi = dm_u + (uint32_t)(s * 4 * A_BUF);
        uint32_t aLo = aHi + 2 * A_BUF;
        uint32_t bHi = dm_u + (uint32_t)(8 * A_BUF + s * 4 * B_BUF2);
        uint32_t bLo = bHi + 2 * B_BUF2;

        {
            if (do_stats) {
                ssum += pa0.x + pa0.y + pa0.z + pa0.w + pa1.x + pa1.y + pa1.z + pa1.w
                      + pa2.x + pa2.y + pa2.z + pa2.w + pa3.x + pa3.y + pa3.z + pa3.w;
                sqsum += pa0.x*pa0.x + pa0.y*pa0.y + pa0.z*pa0.z + pa0.w*pa0.w
                       + pa1.x*pa1.x + pa1.y*pa1.y + pa1.z*pa1.z + pa1.w*pa1.w
                       + pa2.x*pa2.x + pa2.y*pa2.y + pa2.z*pa2.z + pa2.w*pa2.w
                       + pa3.x*pa3.x + pa3.y*pa3.y + pa3.z*pa3.z + pa3.w*pa3.w;
            }
            unsigned h0, h1, h2, h3, h4, h5, h6, h7;
            unsigned l0, l1, l2, l3, l4, l5, l6, l7;
            split2(pa0.x, pa0.y, h0, l0); split2(pa0.z, pa0.w, h1, l1);
            split2(pa1.x, pa1.y, h2, l2); split2(pa1.z, pa1.w, h3, l3);
            split2(pa2.x, pa2.y, h4, l4); split2(pa2.z, pa2.w, h5, l5);
            split2(pa3.x, pa3.y, h6, l6); split2(pa3.z, pa3.w, h7, l7);
            STS16(aHi + ast, h0, h1, h2, h3);
            STS16(aHi + ast + 16, h4, h5, h6, h7);
            STS16(aLo + ast, l0, l1, l2, l3);
            STS16(aLo + ast + 16, l4, l5, l6, l7);
            split2(pb0.x, pb0.y, h0, l0); split2(pb0.z, pb0.w, h1, l1);
            split2(pb1.x, pb1.y, h2, l2); split2(pb1.z, pb1.w, h3, l3);
            STS16(bHi + bst, h0, h1, h2, h3);
            STS16(bLo + bst, l0, l1, l2, l3);
        }

        if (cc + 1 < L) {
            int k0 = (cc + 1) * 32;
            const float* an = ap + k0;
            const float* bn = bp + (long long)k0 * ldb;
            float4 zz = make_float4(0.f, 0.f, 0.f, 0.f);
            pa0 = aok ? *(const float4*)(an)      : zz;
            pa1 = aok ? *(const float4*)(an + 4)  : zz;
            pa2 = aok ? *(const float4*)(an + 8)  : zz;
            pa3 = aok ? *(const float4*)(an + 12) : zz;
            pb0 = bok0 ? *(const float4*)(bn)     : zz;
            pb1 = bok1 ? *(const float4*)(bn + 4) : zz;
        }

        __syncthreads();

        #pragma unroll
        for (int kk = 0; kk < 2; kk++) {
            uint32_t ah[2][4], al[2][4], bh[2][4], bl[2][4];
            #pragma unroll
            for (int mt = 0; mt < 2; mt++) {
                uint32_t ro = (uint32_t)((wm * 32 + mt * 16) * HSTRIDE) * 2 + a_off + kk * 32;
                ldm_x4(ah[mt], aHi + ro);
                ldm_x4(al[mt], aLo + ro);
            }
            #pragma unroll
            for (int nt2 = 0; nt2 < 2; nt2++) {
                uint32_t bo = (uint32_t)(kk * 16 * BST2) * 2 + b_off
                            + (uint32_t)((wn * 32 + nt2 * 16) * 2);
                ldm_x4t(bh[nt2], bHi + bo);
                ldm_x4t(bl[nt2], bLo + bo);
            }
            #pragma unroll
            for (int nt2 = 0; nt2 < 2; nt2++)
                #pragma unroll
                for (int mt = 0; mt < 2; mt++) {
                    mma16816(acc[mt][nt2 * 2],     ah[mt], bh[nt2]);
                    mma16816(acc[mt][nt2 * 2 + 1], ah[mt], bh[nt2] + 2);
                }
            #pragma unroll
            for (int nt2 = 0; nt2 < 2; nt2++)
                #pragma unroll
                for (int mt = 0; mt < 2; mt++) {
                    mma16816(acc[mt][nt2 * 2],     ah[mt], bl[nt2]);
                    mma16816(acc[mt][nt2 * 2 + 1], ah[mt], bl[nt2] + 2);
                }
            #pragma unroll
            for (int nt2 = 0; nt2 < 2; nt2++)
                #pragma unroll
                for (int mt = 0; mt < 2; mt++) {
                    mma16816(acc[mt][nt2 * 2],     al[mt], bh[nt2]);
                    mma16816(acc[mt][nt2 * 2 + 1], al[mt], bh[nt2] + 2);
                }
        }
        __syncthreads();
    }

    if (do_stats && aok) {
        float s2 = ssum + __shfl_xor_sync(0xffffffffu, ssum, 1);
        float q2 = sqsum + __shfl_xor_sync(0xffffffffu, sqsum, 1);
        if ((tid & 1) == 0) {
            float m = s2 / (float)DD;
            stats_mean[m0 + ar] = m;
            stats_rstd[m0 + ar] = rsqrtf(q2 / (float)DD - m * m + EPS);
        }
    }

    int rr = lid >> 2, cc2 = (lid & 3) * 2;
    #pragma unroll
    for (int mt = 0; mt < 2; mt++) {
        #pragma unroll
        for (int nt = 0; nt < 4; nt++) {
            int row = m0 + wm * 32 + mt * 16 + rr;
            int col = n0 + wn * 32 + nt * 8 + cc2;
            if (col < Nvalid) {
                if (row < M)
                    *(float2*)(Cb + (long long)row * ldc + col) =
                        make_float2(acc[mt][nt][0], acc[mt][nt][1]);
                if (row + 8 < M)
                    *(float2*)(Cb + (long long)(row + 8) * ldc + col) =
                        make_float2(acc[mt][nt][2], acc[mt][nt][3]);
            }
        }
    }
}

// ===== hmma2: fp16 2-term + optional fused Y epilogue =====
__global__ void __launch_bounds__(256, 2)
hmma2(const float* __restrict__ A, long long lda, long long abatch,
      const float* __restrict__ B, long long ldb, long long bbatch,
      float* __restrict__ Cc, long long ldc, long long cbatch, long long csplit,
      int M, int Nvalid, int Ktot, int nsplit,
      const float* __restrict__ yg, const float* __restrict__ ys) {
    extern __shared__ __nv_bfloat16 dynsm[];
    uint32_t dm_u = smem_u32(dynsm);

    int tid = threadIdx.x, wid = tid >> 5, lid = tid & 31;
    int z = blockIdx.z;
    int batch = z / nsplit, split = z - batch * nsplit;
    int n0 = blockIdx.x * 64, m0 = blockIdx.y * 128;
    int Kchunk = Ktot / nsplit, kbeg = split * Kchunk;
    int L = Kchunk / 32;

    const float* Ab = A + abatch * batch;
    const float* Bb = B + bbatch * batch;
    float* Cb = Cc + cbatch * batch + csplit * split;

    int ar = tid >> 1, ac = (tid & 1) * 16;
    bool aok = (m0 + ar) < M;
    const float* ap = Ab + (long long)(m0 + ar) * lda + kbeg + ac;
    int kb = tid >> 3, cb = (tid & 7) * 8;
    const float* bp = Bb + (long long)(kbeg + kb) * ldb + n0 + cb;
    bool bok0 = (n0 + cb) < Nvalid, bok1 = (n0 + cb + 4) < Nvalid;

    int wm = wid >> 1, wn = wid & 1;
    float acc[2][4][4];
    #pragma unroll
    for (int a1 = 0; a1 < 2; a1++)
        #pragma unroll
        for (int b1 = 0; b1 < 4; b1++)
            #pragma unroll
            for (int c1 = 0; c1 < 4; c1++) acc[a1][b1][c1] = 0.f;

    uint32_t a_off = (uint32_t)(((lid & 15)) * HSTRIDE + (lid >> 4) * 8) * 2;
    uint32_t b_off = (uint32_t)(((lid & 15)) * BST2 + ((lid >> 4) << 3)) * 2;
    uint32_t ast = (uint32_t)(ar * HSTRIDE + ac) * 2;
    uint32_t bst = (uint32_t)(kb * BST2 + cb) * 2;

    float4 pa0, pa1, pa2, pa3, pb0, pb1;
    {
        float4 zz = make_float4(0.f, 0.f, 0.f, 0.f);
        pa0 = aok ? *(const float4*)(ap)      : zz;
        pa1 = aok ? *(const float4*)(ap + 4)  : zz;
        pa2 = aok ? *(const float4*)(ap + 8)  : zz;
        pa3 = aok ? *(const float4*)(ap + 12) : zz;
        pb0 = bok0 ? *(const float4*)(bp)     : zz;
        pb1 = bok1 ? *(const float4*)(bp + 4) : zz;
    }

    for (int cc = 0; cc < L; cc++) {
        int s = cc & 1;
        uint32_t aHi = dm_u + (uint32_t)(s * 4 * A_BUF);
        uint32_t aLo = aHi + 2 * A_BUF;
        uint32_t bB  = dm_u + (uint32_t)(8 * A_BUF + s * 2 * B_BUF2);

        {
            unsigned h0, h1, h2, h3, h4, h5, h6, h7;
            unsigned l0, l1, l2, l3, l4, l5, l6, l7;
            split2h(pa0.x, pa0.y, h0, l0); split2h(pa0.z, pa0.w, h1, l1);
            split2h(pa1.x, pa1.y, h2, l2); split2h(pa1.z, pa1.w, h3, l3);
            split2h(pa2.x, pa2.y, h4, l4); split2h(pa2.z, pa2.w, h5, l5);
            split2h(pa3.x, pa3.y, h6, l6); split2h(pa3.z, pa3.w, h7, l7);
            STS16(aHi + ast, h0, h1, h2, h3);
            STS16(aHi + ast + 16, h4, h5, h6, h7);
            STS16(aLo + ast, l0, l1, l2, l3);
            STS16(aLo + ast + 16, l4, l5, l6, l7);
            h0 = packh(pb0.x, pb0.y); h1 = packh(pb0.z, pb0.w);
            h2 = packh(pb1.x, pb1.y); h3 = packh(pb1.z, pb1.w);
            STS16(bB + bst, h0, h1, h2, h3);
        }

        if (cc + 1 < L) {
            int k0 = (cc + 1) * 32;
            const float* an = ap + k0;
            const float* bn = bp + (long long)k0 * ldb;
            float4 zz = make_float4(0.f, 0.f, 0.f, 0.f);
            pa0 = aok ? *(const float4*)(an)      : zz;
            pa1 = aok ? *(const float4*)(an + 4)  : zz;
            pa2 = aok ? *(const float4*)(an + 8)  : zz;
            pa3 = aok ? *(const float4*)(an + 12) : zz;
            pb0 = bok0 ? *(const float4*)(bn)     : zz;
            pb1 = bok1 ? *(const float4*)(bn + 4) : zz;
        }

        __syncthreads();

        #pragma unroll
        for (int kk = 0; kk < 2; kk++) {
            uint32_t ah[2][4], al[2][4], bh[2][4];
            #pragma unroll
            for (int mt = 0; mt < 2; mt++) {
                uint32_t ro = (uint32_t)((wm * 32 + mt * 16) * HSTRIDE) * 2 + a_off + kk * 32;
                ldm_x4(ah[mt], aHi + ro);
                ldm_x4(al[mt], aLo + ro);
            }
            #pragma unroll
            for (int nt2 = 0; nt2 < 2; nt2++) {
                uint32_t bo = (uint32_t)(kk * 16 * BST2) * 2 + b_off
                            + (uint32_t)((wn * 32 + nt2 * 16) * 2);
                ldm_x4t(bh[nt2], bB + bo);
            }
            #pragma unroll
            for (int nt2 = 0; nt2 < 2; nt2++)
                #pragma unroll
                for (int mt = 0; mt < 2; mt++) {
                    mma16816h(acc[mt][nt2 * 2],     ah[mt], bh[nt2]);
                    mma16816h(acc[mt][nt2 * 2 + 1], ah[mt], bh[nt2] + 2);
                }
            #pragma unroll
            for (int nt2 = 0; nt2 < 2; nt2++)
                #pragma unroll
                for (int mt = 0; mt < 2; mt++) {
                    mma16816h(acc[mt][nt2 * 2],     al[mt], bh[nt2]);
                    mma16816h(acc[mt][nt2 * 2 + 1], al[mt], bh[nt2] + 2);
                }
        }
        __syncthreads();
    }

    int rr = lid >> 2, cc2 = (lid & 3) * 2;
    if (yg == nullptr) {
        #pragma unroll
        for (int mt = 0; mt < 2; mt++) {
            #pragma unroll
            for (int nt = 0; nt < 4; nt++) {
                int row = m0 + wm * 32 + mt * 16 + rr;
                int col = n0 + wn * 32 + nt * 8 + cc2;
                if (col < Nvalid) {
                    if (row < M)
                        *(float2*)(Cb + (long long)row * ldc + col) =
                            make_float2(acc[mt][nt][0], acc[mt][nt][1]);
                    if (row + 8 < M)
                        *(float2*)(Cb + (long long)(row + 8) * ldc + col) =
                            make_float2(acc[mt][nt][2], acc[mt][nt][3]);
                }
            }
        }
    } else {
        // fused Y epilogue (AX only: M=128, m0=0, Nvalid=DD, nsplit=1)
        #pragma unroll
        for (int mt = 0; mt < 2; mt++) {
            int rloc = wm * 32 + mt * 16 + rr;
            float sv0 = ys[batch * 128 + rloc];
            float sv1 = ys[batch * 128 + rloc + 8];
            long long yr0 = ((long long)(rloc >> 4) * LATROWS + batch * NL + (rloc & 15));
            int r2 = rloc + 8;
            long long yr1 = ((long long)(r2 >> 4) * LATROWS + batch * NL + (r2 & 15));
            #pragma unroll
            for (int nt = 0; nt < 4; nt++) {
                int col = n0 + wn * 32 + nt * 8 + cc2;
                float g0 = yg[col], g1 = yg[col + 1];
                *(float2*)(Cc + yr0 * DD + col) =
                    make_float2((acc[mt][nt][0] - sv0) * g0, (acc[mt][nt][1] - sv0) * g1);
                *(float2*)(Cc + yr1 * DD + col) =
                    make_float2((acc[mt][nt][2] - sv1) * g0, (acc[mt][nt][3] - sv1) * g1);
            }
        }
    }
}

// ---------------- generic split reduce + epilogue ----------------
__global__ void reduce_kernel(const float* __restrict__ parts, long long pstride, int nsplit,
                              float* __restrict__ out, long long n,
                              const float* __restrict__ addsrc, int add_mode,
                              const float* __restrict__ bias, int bias_period,
                              int do_gelu) {
    long long i = (long long)blockIdx.x * 256 + threadIdx.x;
    if (i >= n) return;
    float s = 0.f;
    for (int p = 0; p < nsplit; p++) s += parts[p * pstride + i];
    if (bias) s += bias[i % bias_period];
    if (do_gelu) s = 0.5f * s * (1.0f + erff(s * 0.70710678118654752f));
    if (add_mode == 1) s += addsrc[i];
    else if (add_mode == 2) {
        long long r = i >> 12;
        s += addsrc[((r & 15) << 12) + (i & 4095)];
    }
    out[i] = s;
}

// ---------------- qt_all ----------------
__global__ void qt_all_kernel(const float* __restrict__ qp, const float* __restrict__ wkv,
                              const float* __restrict__ g,
                              float* __restrict__ QTT, float* __restrict__ QG) {
    __shared__ float qs[NL * INNER];
    for (int i = threadIdx.x; i < NL * INNER; i += 256) {
        float s = 0.f;
        #pragma unroll
        for (int p = 0; p < 8; p++) s += qp[p * NL * INNER + i];
        qs[i] = s;
    }
    __syncthreads();
    int d = blockIdx.x * 32 + (threadIdx.x >> 3);
    int h = threadIdx.x & 7;
    const float* wrow = wkv + (long long)d * 1536 + h * DHH;
    float acc[NL];
    #pragma unroll
    for (int i = 0; i < NL; i++) acc[i] = 0.f;
    for (int dh = 0; dh < DHH; dh++) {
        float w = wrow[dh];
        #pragma unroll
        for (int i = 0; i < NL; i++) acc[i] = fmaf(qs[i * INNER + h * DHH + dh], w, acc[i]);
    }
    float gd = g[d];
    #pragma unroll
    for (int i = 0; i < NL; i++) {
        int ih = h * NL + i;
        QTT[(long long)d * 128 + ih] = acc[i];
        QG[(long long)d * 128 + ih] = acc[i] * gd;
    }
}

// ---------------- parallel u/v ----------------
__global__ void uv_part_kernel(const float* __restrict__ QTT, const float* __restrict__ g,
                               const float* __restrict__ b,
                               float* __restrict__ up, float* __restrict__ vp) {
    int ih = threadIdx.x;
    int c = blockIdx.x;
    float uu = 0.f, vv = 0.f;
    for (int d = c * 256; d < (c + 1) * 256; d++) {
        float t = QTT[(long long)d * 128 + ih];
        uu = fmaf(t, g[d], uu);
        vv = fmaf(t, b[d], vv);
    }
    up[c * 128 + ih] = uu;
    vp[c * 128 + ih] = vv;
}
__global__ void uv_comb_kernel(const float* __restrict__ up, const float* __restrict__ vp,
                               float* __restrict__ u, float* __restrict__ v) {
    int ih = threadIdx.x;
    float uu = 0.f, vv = 0.f;
    #pragma unroll
    for (int c = 0; c < 16; c++) { uu += up[c * 128 + ih]; vv += vp[c * 128 + ih]; }
    u[ih] = uu; v[ih] = vv;
}

// ---------------- parallel bv ----------------
__global__ void bv_part_kernel(const float* __restrict__ b, const float* __restrict__ wkv,
                               float* __restrict__ bvp) {
    int e = blockIdx.x * 128 + threadIdx.x;
    int c = blockIdx.y;
    float a = 0.f;
    for (int d = c * 256; d < (c + 1) * 256; d++)
        a = fmaf(b[d], wkv[(long long)d * 1536 + INNER + e], a);
    bvp[c * INNER + e] = a;
}
__global__ void bv_comb_kernel(const float* __restrict__ bvp, float* __restrict__ bv) {
    int e = blockIdx.x * 128 + threadIdx.x;
    float a = 0.f;
    #pragma unroll
    for (int c = 0; c < 16; c++) a += bvp[c * INNER + e];
    bv[e] = a;
}

// ---------------- attention softmax ----------------
__global__ void attn_kernel(const float* __restrict__ guid, const void* __restrict__ mask,
                            const float* __restrict__ S0, const float* __restrict__ mean,
                            const float* __restrict__ rstd,
                            const float* __restrict__ u, const float* __restrict__ v,
                            float* __restrict__ C, float* __restrict__ s_out) {
    extern __shared__ float sm[];
    float* sim = sm;
    float* rj  = sim + NL * NN;
    float* mj  = rj + NN;
    float* gu  = mj + NN;
    float* mk  = gu + NN;
    float* us  = mk + NN;
    float* vs  = us + NL;

    int bt = blockIdx.x >> 3;
    int h  = blockIdx.x & 7;
    int tid = threadIdx.x;
    int kind = g_mask_kind;

    for (int j = tid; j < NN; j += 256) {
        rj[j] = rstd[bt * NN + j];
        mj[j] = mean[bt * NN + j];
        gu[j] = guid[bt * NN + j];
        mk[j] = (kind == 1) ? (float)((const int*)mask)[bt * NN + j]
                            : (float)((const unsigned char*)mask)[bt * NN + j];
    }
    if (tid < NL) { us[tid] = u[h * NL + tid]; vs[tid] = v[h * NL + tid]; }
    __syncthreads();

    for (int idx = tid; idx < NL * NN; idx += 256) {
        int j = idx >> 4, i = idx & 15;
        float t = S0[((size_t)bt * NN + j) * 128 + h * NL + i];
        sim[i * NN + j] = ATTN_SCALE * (rj[j] * t - rj[j] * mj[j] * us[i] + vs[i]);
    }
    __syncthreads();

    int warp = tid >> 5, lane = tid & 31;
    for (int r = warp; r < NL; r += 8) {
        float* srow = sim + r * NN;
        float m0 = -FLT_MAX;
        for (int j = lane; j < NN; j += 32) m0 = fmaxf(m0, srow[j]);
        #pragma unroll
        for (int o = 16; o; o >>= 1) m0 = fmaxf(m0, __shfl_xor_sync(0xffffffffu, m0, o));

        float m1 = -FLT_MAX;
        for (int j = lane; j < NN; j += 32) {
            float s = srow[j] - m0;
            if (mk[j] != 0.f) s = -3.402823466e38f;
            s *= gu[j];
            srow[j] = s;
            m1 = fmaxf(m1, s);
        }
        #pragma unroll
        for (int o = 16; o; o >>= 1) m1 = fmaxf(m1, __shfl_xor_sync(0xffffffffu, m1, o));

        float sum = 0.f;
        for (int j = lane; j < NN; j += 32) {
            float e = expf(srow[j] - m1);
            srow[j] = e;
            sum += e;
        }
        #pragma unroll
        for (int o = 16; o; o >>= 1) sum += __shfl_xor_sync(0xffffffffu, sum, o);
        float inv = 1.f / sum;

        float sacc = 0.f;
        float* crow = C + ((size_t)bt * 128 + h * NL + r) * NN;
        for (int j = lane; j < NN; j += 32) {
            float a = srow[j] * inv;
            float c = a * rj[j];
            crow[j] = c;
            sacc = fmaf(c, mj[j], sacc);
        }
        #pragma unroll
        for (int o = 16; o; o >>= 1) sacc += __shfl_xor_sync(0xffffffffu, sacc, o);
        if (lane == 0) s_out[bt * 128 + h * NL + r] = sacc;
    }
}

// ---------------- launch ----------------
extern "C" void kernel_launch(void* const* d_in, const int* in_sizes, int n_in,
                              void* d_out, int out_size) {
    const float* x       = (const float*)d_in[0];
    const float* guid    = (const float*)d_in[1];
    const void*  mask    = d_in[2];
    const float* latents = (const float*)d_in[3];
    const float* nm_g    = (const float*)d_in[4];
    const float* nm_b    = (const float*)d_in[5];
    const float* nl_g    = (const float*)d_in[6];
    const float* nl_b    = (const float*)d_in[7];
    const float* wq      = (const float*)d_in[8];
    const float* wkv     = (const float*)d_in[9];
    const float* wout    = (const float*)d_in[10];
    const float* ff_g    = (const float*)d_in[11];
    const float* ff_b    = (const float*)d_in[12];
    const float* w1      = (const float*)d_in[13];
    const float* w2      = (const float*)d_in[14];
    const float* fn_g    = (const float*)d_in[15];
    const float* fn_b    = (const float*)d_in[16];
    float* out = (float*)d_out;

    float *p_mean, *p_rstd, *p_ql, *p_qp, *p_QTT, *p_QG, *p_u, *p_v, *p_bv;
    float *p_up, *p_vp, *p_bvp;
    float *p_S0, *p_C, *p_s, *p_Y, *p_Vp, *p_attnv, *p_woutp;
    float *p_lat1, *p_ffln, *p_ff1p, *p_h1, *p_ff2p, *p_lat2;
    cudaGetSymbolAddress((void**)&p_mean, g_mean);
    cudaGetSymbolAddress((void**)&p_rstd, g_rstd);
    cudaGetSymbolAddress((void**)&p_ql, g_ql);
    cudaGetSymbolAddress((void**)&p_qp, g_qp);
    cudaGetSymbolAddress((void**)&p_QTT, g_QTT);
    cudaGetSymbolAddress((void**)&p_QG, g_QG);
    cudaGetSymbolAddress((void**)&p_u, g_u);
    cudaGetSymbolAddress((void**)&p_v, g_v);
    cudaGetSymbolAddress((void**)&p_bv, g_bv);
    cudaGetSymbolAddress((void**)&p_up, g_up);
    cudaGetSymbolAddress((void**)&p_vp, g_vp);
    cudaGetSymbolAddress((void**)&p_bvp, g_bvp);
    cudaGetSymbolAddress((void**)&p_S0, g_S0);
    cudaGetSymbolAddress((void**)&p_C, g_C);
    cudaGetSymbolAddress((void**)&p_s, g_s);
    cudaGetSymbolAddress((void**)&p_Y, g_Y);
    cudaGetSymbolAddress((void**)&p_Vp, g_Vp);
    cudaGetSymbolAddress((void**)&p_attnv, g_attnv);
    cudaGetSymbolAddress((void**)&p_woutp, g_woutp);
    cudaGetSymbolAddress((void**)&p_lat1, g_lat1);
    cudaGetSymbolAddress((void**)&p_ffln, g_ffln);
    cudaGetSymbolAddress((void**)&p_ff1p, g_ff1p);
    cudaGetSymbolAddress((void**)&p_h1, g_h1);
    cudaGetSymbolAddress((void**)&p_ff2p, g_ff2p);
    cudaGetSymbolAddress((void**)&p_lat2, g_lat2);

    cudaFuncSetAttribute(hmma3, cudaFuncAttributeMaxDynamicSharedMemorySize, HSMEM3);
    cudaFuncSetAttribute(hmma2, cudaFuncAttributeMaxDynamicSharedMemorySize, HSMEM2);

    // #1 ql = LN(latents)
    ln_rows_kernel<<<NL, 256>>>(latents, p_ql, nl_g, nl_b);
    // #2 qp = ql @ wq partials (split-K 8)
    hmma3<<<dim3(INNER / 64, 1, 8), 256, HSMEM3>>>(p_ql, DD, 0, wq, INNER, 0,
                                                   p_qp, INNER, 0, NL * INNER,
                                                   NL, INNER, DD, 8, nullptr, nullptr);
    // #3 qt_all
    qt_all_kernel<<<DD / 32, 256>>>(p_qp, wkv, nm_g, p_QTT, p_QG);

    // #4 S0 = x @ QG + fused x row stats
    hmma3<<<dim3(2, XROWS / 128, 1), 256, HSMEM3>>>(x, DD, 0, p_QG, 128, 0,
                                                    p_S0, 128, 0, 0,
                                                    XROWS, 128, DD, 1, p_mean, p_rstd);

    // u/v (parallel), bv (parallel), mask-kind
    uv_part_kernel<<<16, 128>>>(p_QTT, nm_g, nm_b, p_up, p_vp);
    uv_comb_kernel<<<1, 128>>>(p_up, p_vp, p_u, p_v);
    bv_part_kernel<<<dim3(INNER / 128, 16), 128>>>(nm_b, wkv, p_bvp);
    bv_comb_kernel<<<INNER / 128, 128>>>(p_bvp, p_bv);
    detect_mask_kernel<<<1, 256>>>((const unsigned int*)mask);

    // softmax -> C, s
    {
        int smemb = (NL * NN + 4 * NN + 2 * NL) * (int)sizeof(float);
        cudaFuncSetAttribute(attn_kernel, cudaFuncAttributeMaxDynamicSharedMemorySize, smemb);
        attn_kernel<<<BT * HH, 256, smemb>>>(guid, mask, p_S0, p_mean, p_rstd,
                                             p_u, p_v, p_C, p_s);
    }

    // AX[bt] = C[bt] @ x[bt] with fused Y epilogue
    hmma2<<<dim3(DD / 64, 1, BT), 256, HSMEM2>>>(
        p_C, NN, (long long)128 * NN, x, DD, (long long)NN * DD,
        p_Y, DD, 0, 0, 128, DD, NN, 1, nm_g, p_s);

    // attnV (split-K 8)
    hmma2<<<dim3(2, 2, HH * 8), 256, HSMEM2>>>(
        p_Y, DD, (long long)LATROWS * DD, wkv + INNER, 1536, 96,
        p_Vp, INNER, 96, (long long)LATROWS * INNER, LATROWS, 96, DD, 8,
        nullptr, nullptr);
    reduce_kernel<<<(LATROWS * INNER + 255) / 256, 256>>>(
        p_Vp, (long long)LATROWS * INNER, 8, p_attnv, LATROWS * INNER,
        nullptr, 0, p_bv, INNER, 0);

    // lat1 = attnv @ wout + latents (split-K 2)
    hmma2<<<dim3(DD / 64, 2, 2), 256, HSMEM2>>>(
        p_attnv, INNER, 0, wout, DD, 0,
        p_woutp, DD, 0, (long long)LATROWS * DD, LATROWS, DD, INNER, 2,
        nullptr, nullptr);
    reduce_kernel<<<(LATROWS * DD + 255) / 256, 256>>>(
        p_woutp, (long long)LATROWS * DD, 2, p_lat1, LATROWS * DD,
        latents, 2, nullptr, 1, 0);

    // FF
    ln_rows_kernel<<<LATROWS, 256>>>(p_lat1, p_ffln, ff_g, ff_b);
    hmma2<<<dim3(FF / 64, 2, 2), 256, HSMEM2>>>(
        p_ffln, DD, 0, w1, FF, 0,
        p_ff1p, FF, 0, (long long)LATROWS * FF, LATROWS, FF, DD, 2,
        nullptr, nullptr);
    reduce_kernel<<<((long long)LATROWS * FF + 255) / 256, 256>>>(
        p_ff1p, (long long)LATROWS * FF, 2, p_h1, (long long)LATROWS * FF,
        nullptr, 0, nullptr, 1, 1);
    hmma2<<<dim3(DD / 64, 2, 2), 256, HSMEM2>>>(
        p_h1, FF, 0, w2, DD, 0,
        p_ff2p, DD, 0, (long long)LATROWS * DD, LATROWS, DD, FF, 2,
        nullptr, nullptr);
    reduce_kernel<<<(LATROWS * DD + 255) / 256, 256>>>(
        p_ff2p, (long long)LATROWS * DD, 2, p_lat2, LATROWS * DD,
        p_lat1, 1, nullptr, 1, 0);

    // final LN
    ln_rows_kernel<<<LATROWS, 256>>>(p_lat2, out, fn_g, fn_b);
}

// round 16
// speedup vs baseline: 1.1135x; 1.1135x over previous
#include <cuda_runtime.h>
#include <cuda_bf16.h>
#include <cuda_fp16.h>
#include <cfloat>
#include <math.h>
#include <stdint.h>

// ---------------- problem constants ----------------
#define NN 1792
#define DD 4096
#define HH 8
#define DHH 96
#define INNER 768
#define NL 16
#define FF 8192
#define BT 16
#define XROWS 28672
#define LATROWS 256
#define EPS 1e-5f
#define ATTN_SCALE 0.10206207261596577f

// ---------------- scratch ----------------
__device__ float g_mean[XROWS];
__device__ float g_rstd[XROWS];
__device__ int   g_mask_kind;

__device__ float g_ql[NL * DD];
__device__ float g_qp[16 * NL * INNER];

__device__ float g_QTT[DD * 128];
__device__ float g_QG[DD * 128];
__device__ float g_u[128];
__device__ float g_v[128];
__device__ float g_bv[INNER];
__device__ float g_up[16 * 128];
__device__ float g_vp[16 * 128];
__device__ float g_bvp[16 * INNER];

__device__ float g_S0[(size_t)XROWS * 128];
__device__ float g_C[(size_t)BT * 128 * NN];
__device__ float g_s[BT * 128];
__device__ float g_Y[(size_t)HH * LATROWS * DD];

__device__ float g_Vp[16 * (size_t)LATROWS * INNER];
__device__ float g_attnv[LATROWS * INNER];
__device__ float g_woutp[4 * (size_t)LATROWS * DD];
__device__ float g_lat1[LATROWS * DD];
__device__ float g_ffln[LATROWS * DD];
__device__ float g_ff1p[2 * (size_t)LATROWS * FF];
__device__ float g_h1[(size_t)LATROWS * FF];
__device__ float g_ff2p[4 * (size_t)LATROWS * DD];
__device__ float g_lat2[LATROWS * DD];

// ---------------- helpers ----------------
__device__ __forceinline__ uint32_t smem_u32(const void* p) {
    uint32_t a;
    asm("{ .reg .u64 t; cvta.to.shared.u64 t, %1; cvt.u32.u64 %0, t; }" : "=r"(a) : "l"(p));
    return a;
}
__device__ __forceinline__ void ldm_x4(uint32_t* r, uint32_t addr) {
    asm volatile("ldmatrix.sync.aligned.m8n8.x4.shared.b16 {%0,%1,%2,%3}, [%4];"
                 : "=r"(r[0]), "=r"(r[1]), "=r"(r[2]), "=r"(r[3]) : "r"(addr));
}
__device__ __forceinline__ void ldm_x4t(uint32_t* r, uint32_t addr) {
    asm volatile("ldmatrix.sync.aligned.m8n8.x4.trans.shared.b16 {%0,%1,%2,%3}, [%4];"
                 : "=r"(r[0]), "=r"(r[1]), "=r"(r[2]), "=r"(r[3]) : "r"(addr));
}
__device__ __forceinline__ void mma16816(float* c, const uint32_t* a, const uint32_t* b) {
    asm volatile(
        "mma.sync.aligned.m16n8k16.row.col.f32.bf16.bf16.f32 "
        "{%0,%1,%2,%3}, {%4,%5,%6,%7}, {%8,%9}, {%0,%1,%2,%3};"
        : "+f"(c[0]), "+f"(c[1]), "+f"(c[2]), "+f"(c[3])
        : "r"(a[0]), "r"(a[1]), "r"(a[2]), "r"(a[3]), "r"(b[0]), "r"(b[1]));
}
__device__ __forceinline__ void mma16816h(float* c, const uint32_t* a, const uint32_t* b) {
    asm volatile(
        "mma.sync.aligned.m16n8k16.row.col.f32.f16.f16.f32 "
        "{%0,%1,%2,%3}, {%4,%5,%6,%7}, {%8,%9}, {%0,%1,%2,%3};"
        : "+f"(c[0]), "+f"(c[1]), "+f"(c[2]), "+f"(c[3])
        : "r"(a[0]), "r"(a[1]), "r"(a[2]), "r"(a[3]), "r"(b[0]), "r"(b[1]));
}
__device__ __forceinline__ void split2(float x, float y, unsigned& h, unsigned& l) {
    __nv_bfloat162 hh = __floats2bfloat162_rn(x, y);
    float r0 = x - __bfloat162float(__low2bfloat16(hh));
    float r1 = y - __bfloat162float(__high2bfloat16(hh));
    __nv_bfloat162 ll = __floats2bfloat162_rn(r0, r1);
    h = *reinterpret_cast<unsigned*>(&hh);
    l = *reinterpret_cast<unsigned*>(&ll);
}
__device__ __forceinline__ void split2h(float x, float y, unsigned& h, unsigned& l) {
    __half2 hh = __floats2half2_rn(x, y);
    float r0 = x - __half2float(__low2half(hh));
    float r1 = y - __half2float(__high2half(hh));
    __half2 ll = __floats2half2_rn(r0, r1);
    h = *reinterpret_cast<unsigned*>(&hh);
    l = *reinterpret_cast<unsigned*>(&ll);
}
__device__ __forceinline__ unsigned packh(float x, float y) {
    __half2 hh = __floats2half2_rn(x, y);
    return *reinterpret_cast<unsigned*>(&hh);
}

// ---------------- mask kind detection ----------------
__global__ void detect_mask_kernel(const unsigned int* __restrict__ m) {
    __shared__ unsigned int sh[8];
    unsigned int orv = 0;
    for (int i = threadIdx.x; i < XROWS / 4; i += 256) orv |= m[i];
    #pragma unroll
    for (int o = 16; o; o >>= 1) orv |= __shfl_xor_sync(0xffffffffu, orv, o);
    int w = threadIdx.x >> 5;
    if ((threadIdx.x & 31) == 0) sh[w] = orv;
    __syncthreads();
    if (threadIdx.x == 0) {
        unsigned int t = 0;
        #pragma unroll
        for (int i = 0; i < 8; i++) t |= sh[i];
        g_mask_kind = (t <= 1u) ? 1 : 0;
    }
}

// ---------------- layernorm ----------------
__global__ void ln_rows_kernel(const float* __restrict__ in, float* __restrict__ out,
                               const float* __restrict__ g, const float* __restrict__ b) {
    int row = blockIdx.x;
    const float* xr = in + (size_t)row * DD;
    float s = 0.f, q = 0.f;
    for (int i = threadIdx.x; i < DD; i += blockDim.x) { float v = xr[i]; s += v; q += v * v; }
    #pragma unroll
    for (int o = 16; o; o >>= 1) {
        s += __shfl_xor_sync(0xffffffffu, s, o);
        q += __shfl_xor_sync(0xffffffffu, q, o);
    }
    __shared__ float sh_s[8], sh_q[8];
    __shared__ float m_sh, r_sh;
    int w = threadIdx.x >> 5, l = threadIdx.x & 31;
    if (l == 0) { sh_s[w] = s; sh_q[w] = q; }
    __syncthreads();
    if (threadIdx.x == 0) {
        float S = 0.f, Q = 0.f;
        #pragma unroll
        for (int i = 0; i < 8; i++) { S += sh_s[i]; Q += sh_q[i]; }
        float m = S / (float)DD;
        m_sh = m;
        r_sh = rsqrtf(Q / (float)DD - m * m + EPS);
    }
    __syncthreads();
    float m = m_sh, r = r_sh;
    for (int i = threadIdx.x; i < DD; i += blockDim.x)
        out[(size_t)row * DD + i] = (xr[i] - m) * r * g[i] + b[i];
}

// ================= hmma3: bf16 3-term (R8-proven) =================
#define HSTRIDE 40
#define BST 136
#define A_BUF 5120
#define B_BUF 4352
#define HSMEM3 ((4 * A_BUF + 4 * B_BUF) * 2)
__global__ void __launch_bounds__(256, 1)
hmma3(const float* __restrict__ A, long long lda, long long abatch,
      const float* __restrict__ B, long long ldb, long long bbatch,
      float* __restrict__ Cc, long long ldc, long long cbatch, long long csplit,
      int M, int Nvalid, int Ktot, int nsplit,
      float* __restrict__ stats_mean, float* __restrict__ stats_rstd) {
    extern __shared__ __nv_bfloat16 dynsm[];
    uint32_t dm_u = smem_u32(dynsm);

    int tid = threadIdx.x, wid = tid >> 5, lid = tid & 31;
    int z = blockIdx.z;
    int batch = z / nsplit, split = z - batch * nsplit;
    int n0 = blockIdx.x * 128, m0 = blockIdx.y * 128;
    int Kchunk = Ktot / nsplit, kbeg = split * Kchunk;
    int L = Kchunk / 32;

    const float* Ab = A + abatch * batch;
    const float* Bb = B + bbatch * batch;
    float* Cb = Cc + cbatch * batch + csplit * split;

    int ar = tid >> 1, ac = (tid & 1) * 16;
    bool aok = (m0 + ar) < M;
    const float* ap = Ab + (long long)(m0 + ar) * lda + kbeg + ac;
    int kb = tid >> 3, cb = (tid & 7) * 16;
    const float* bp = Bb + (long long)(kbeg + kb) * ldb + n0 + cb;
    bool bok0 = (n0 + cb) < Nvalid, bok1 = (n0 + cb + 4) < Nvalid;
    bool bok2 = (n0 + cb + 8) < Nvalid, bok3 = (n0 + cb + 12) < Nvalid;

    int wm = wid >> 1, wn = wid & 1;
    float acc[2][8][4];
    #pragma unroll
    for (int a1 = 0; a1 < 2; a1++)
        #pragma unroll
        for (int b1 = 0; b1 < 8; b1++)
            #pragma unroll
            for (int c1 = 0; c1 < 4; c1++) acc[a1][b1][c1] = 0.f;

    uint32_t a_off = (uint32_t)(((lid & 15)) * HSTRIDE + (lid >> 4) * 8) * 2;
    uint32_t b_off = (uint32_t)(((lid & 15)) * BST + ((lid >> 4) << 3)) * 2;
    uint32_t ast_off = (uint32_t)(ar * HSTRIDE + ac) * 2;
    uint32_t bst_off = (uint32_t)(kb * BST + cb) * 2;

    bool do_stats = (stats_mean != nullptr);
    float ssum = 0.f, sqsum = 0.f;

    float4 pa0, pa1, pa2, pa3, pb0, pb1, pb2, pb3;
    {
        float4 zz = make_float4(0.f, 0.f, 0.f, 0.f);
        pa0 = aok ? *(const float4*)(ap)      : zz;
        pa1 = aok ? *(const float4*)(ap + 4)  : zz;
        pa2 = aok ? *(const float4*)(ap + 8)  : zz;
        pa3 = aok ? *(const float4*)(ap + 12) : zz;
        pb0 = bok0 ? *(const float4*)(bp)      : zz;
        pb1 = bok1 ? *(const float4*)(bp + 4)  : zz;
        pb2 = bok2 ? *(const float4*)(bp + 8)  : zz;
        pb3 = bok3 ? *(const float4*)(bp + 12) : zz;
    }

    for (int cc = 0; cc < L; cc++) {
        int s = cc & 1;
        uint32_t aHi = dm_u + (uint32_t)(s * 2 * A_BUF) * 2;
        uint32_t aLo = aHi + A_BUF * 2;
        uint32_t bHi = dm_u + (uint32_t)(4 * A_BUF + s * 2 * B_BUF) * 2;
        uint32_t bLo = bHi + B_BUF * 2;

        {
            if (do_stats) {
                ssum += pa0.x + pa0.y + pa0.z + pa0.w + pa1.x + pa1.y + pa1.z + pa1.w
                      + pa2.x + pa2.y + pa2.z + pa2.w + pa3.x + pa3.y + pa3.z + pa3.w;
                sqsum += pa0.x*pa0.x + pa0.y*pa0.y + pa0.z*pa0.z + pa0.w*pa0.w
                       + pa1.x*pa1.x + pa1.y*pa1.y + pa1.z*pa1.z + pa1.w*pa1.w
                       + pa2.x*pa2.x + pa2.y*pa2.y + pa2.z*pa2.z + pa2.w*pa2.w
                       + pa3.x*pa3.x + pa3.y*pa3.y + pa3.z*pa3.z + pa3.w*pa3.w;
            }
            unsigned h0, h1, h2, h3, h4, h5, h6, h7;
            unsigned l0, l1, l2, l3, l4, l5, l6, l7;
            split2(pa0.x, pa0.y, h0, l0); split2(pa0.z, pa0.w, h1, l1);
            split2(pa1.x, pa1.y, h2, l2); split2(pa1.z, pa1.w, h3, l3);
            split2(pa2.x, pa2.y, h4, l4); split2(pa2.z, pa2.w, h5, l5);
            split2(pa3.x, pa3.y, h6, l6); split2(pa3.z, pa3.w, h7, l7);
            asm volatile("st.shared.v4.b32 [%0], {%1,%2,%3,%4};" ::
                "r"(aHi + ast_off), "r"(h0), "r"(h1), "r"(h2), "r"(h3));
            asm volatile("st.shared.v4.b32 [%0], {%1,%2,%3,%4};" ::
                "r"(aHi + ast_off + 16), "r"(h4), "r"(h5), "r"(h6), "r"(h7));
            asm volatile("st.shared.v4.b32 [%0], {%1,%2,%3,%4};" ::
                "r"(aLo + ast_off), "r"(l0), "r"(l1), "r"(l2), "r"(l3));
            asm volatile("st.shared.v4.b32 [%0], {%1,%2,%3,%4};" ::
                "r"(aLo + ast_off + 16), "r"(l4), "r"(l5), "r"(l6), "r"(l7));
            split2(pb0.x, pb0.y, h0, l0); split2(pb0.z, pb0.w, h1, l1);
            split2(pb1.x, pb1.y, h2, l2); split2(pb1.z, pb1.w, h3, l3);
            split2(pb2.x, pb2.y, h4, l4); split2(pb2.z, pb2.w, h5, l5);
            split2(pb3.x, pb3.y, h6, l6); split2(pb3.z, pb3.w, h7, l7);
            asm volatile("st.shared.v4.b32 [%0], {%1,%2,%3,%4};" ::
                "r"(bHi + bst_off), "r"(h0), "r"(h1), "r"(h2), "r"(h3));
            asm volatile("st.shared.v4.b32 [%0], {%1,%2,%3,%4};" ::
                "r"(bHi + bst_off + 16), "r"(h4), "r"(h5), "r"(h6), "r"(h7));
            asm volatile("st.shared.v4.b32 [%0], {%1,%2,%3,%4};" ::
                "r"(bLo + bst_off), "r"(l0), "r"(l1), "r"(l2), "r"(l3));
            asm volatile("st.shared.v4.b32 [%0], {%1,%2,%3,%4};" ::
                "r"(bLo + bst_off + 16), "r"(l4), "r"(l5), "r"(l6), "r"(l7));
        }

        if (cc + 1 < L) {
            int k0 = (cc + 1) * 32;
            const float* an = ap + k0;
            const float* bn = bp + (long long)k0 * ldb;
            float4 zz = make_float4(0.f, 0.f, 0.f, 0.f);
            pa0 = aok ? *(const float4*)(an)      : zz;
            pa1 = aok ? *(const float4*)(an + 4)  : zz;
            pa2 = aok ? *(const float4*)(an + 8)  : zz;
            pa3 = aok ? *(const float4*)(an + 12) : zz;
            pb0 = bok0 ? *(const float4*)(bn)      : zz;
            pb1 = bok1 ? *(const float4*)(bn + 4)  : zz;
            pb2 = bok2 ? *(const float4*)(bn + 8)  : zz;
            pb3 = bok3 ? *(const float4*)(bn + 12) : zz;
        }

        __syncthreads();

        #pragma unroll
        for (int kk = 0; kk < 2; kk++) {
            uint32_t ah[2][4], al[2][4], bh[4][4], bl[4][4];
            #pragma unroll
            for (int mt = 0; mt < 2; mt++) {
                uint32_t ro = (uint32_t)((wm * 32 + mt * 16) * HSTRIDE) * 2 + a_off + kk * 32;
                ldm_x4(ah[mt], aHi + ro);
                ldm_x4(al[mt], aLo + ro);
            }
            #pragma unroll
            for (int nt2 = 0; nt2 < 4; nt2++) {
                uint32_t bo = (uint32_t)(kk * 16 * BST) * 2 + b_off
                            + (uint32_t)((wn * 64 + nt2 * 16) * 2);
                ldm_x4t(bh[nt2], bHi + bo);
                ldm_x4t(bl[nt2], bLo + bo);
            }
            #pragma unroll
            for (int nt2 = 0; nt2 < 4; nt2++)
                #pragma unroll
                for (int mt = 0; mt < 2; mt++) {
                    mma16816(acc[mt][nt2 * 2],     ah[mt], bh[nt2]);
                    mma16816(acc[mt][nt2 * 2 + 1], ah[mt], bh[nt2] + 2);
                }
            #pragma unroll
            for (int nt2 = 0; nt2 < 4; nt2++)
                #pragma unroll
                for (int mt = 0; mt < 2; mt++) {
                    mma16816(acc[mt][nt2 * 2],     ah[mt], bl[nt2]);
                    mma16816(acc[mt][nt2 * 2 + 1], ah[mt], bl[nt2] + 2);
                }
            #pragma unroll
            for (int nt2 = 0; nt2 < 4; nt2++)
                #pragma unroll
                for (int mt = 0; mt < 2; mt++) {
                    mma16816(acc[mt][nt2 * 2],     al[mt], bh[nt2]);
                    mma16816(acc[mt][nt2 * 2 + 1], al[mt], bh[nt2] + 2);
                }
        }
        __syncthreads();
    }

    if (do_stats && aok) {
        float s2 = ssum + __shfl_xor_sync(0xffffffffu, ssum, 1);
        float q2 = sqsum + __shfl_xor_sync(0xffffffffu, sqsum, 1);
        if ((tid & 1) == 0) {
            float m = s2 / (float)DD;
            stats_mean[m0 + ar] = m;
            stats_rstd[m0 + ar] = rsqrtf(q2 / (float)DD - m * m + EPS);
        }
    }

    int rr = lid >> 2, cc2 = (lid & 3) * 2;
    #pragma unroll
    for (int mt = 0; mt < 2; mt++) {
        #pragma unroll
        for (int nt = 0; nt < 8; nt++) {
            int row = m0 + wm * 32 + mt * 16 + rr;
            int col = n0 + wn * 64 + nt * 8 + cc2;
            if (col < Nvalid) {
                if (row < M)
                    *(float2*)(Cb + (long long)row * ldc + col) =
                        make_float2(acc[mt][nt][0], acc[mt][nt][1]);
                if (row + 8 < M)
                    *(float2*)(Cb + (long long)(row + 8) * ldc + col) =
                        make_float2(acc[mt][nt][2], acc[mt][nt][3]);
            }
        }
    }
}

// ============ hmma2: fp16 2-term (R8-proven) + optional fused Y epilogue =====
#define HSMEM2 ((4 * A_BUF + 2 * B_BUF) * 2)
__global__ void __launch_bounds__(256, 1)
hmma2(const float* __restrict__ A, long long lda, long long abatch,
      const float* __restrict__ B, long long ldb, long long bbatch,
      float* __restrict__ Cc, long long ldc, long long cbatch, long long csplit,
      int M, int Nvalid, int Ktot, int nsplit,
      const float* __restrict__ yg, const float* __restrict__ ys) {
    extern __shared__ __nv_bfloat16 dynsm[];
    uint32_t dm_u = smem_u32(dynsm);

    int tid = threadIdx.x, wid = tid >> 5, lid = tid & 31;
    int z = blockIdx.z;
    int batch = z / nsplit, split = z - batch * nsplit;
    int n0 = blockIdx.x * 128, m0 = blockIdx.y * 128;
    int Kchunk = Ktot / nsplit, kbeg = split * Kchunk;
    int L = Kchunk / 32;

    const float* Ab = A + abatch * batch;
    const float* Bb = B + bbatch * batch;
    float* Cb = Cc + cbatch * batch + csplit * split;

    int ar = tid >> 1, ac = (tid & 1) * 16;
    bool aok = (m0 + ar) < M;
    const float* ap = Ab + (long long)(m0 + ar) * lda + kbeg + ac;
    int kb = tid >> 3, cb = (tid & 7) * 16;
    const float* bp = Bb + (long long)(kbeg + kb) * ldb + n0 + cb;
    bool bok0 = (n0 + cb) < Nvalid, bok1 = (n0 + cb + 4) < Nvalid;
    bool bok2 = (n0 + cb + 8) < Nvalid, bok3 = (n0 + cb + 12) < Nvalid;

    int wm = wid >> 1, wn = wid & 1;
    float acc[2][8][4];
    #pragma unroll
    for (int a1 = 0; a1 < 2; a1++)
        #pragma unroll
        for (int b1 = 0; b1 < 8; b1++)
            #pragma unroll
            for (int c1 = 0; c1 < 4; c1++) acc[a1][b1][c1] = 0.f;

    uint32_t a_off = (uint32_t)(((lid & 15)) * HSTRIDE + (lid >> 4) * 8) * 2;
    uint32_t b_off = (uint32_t)(((lid & 15)) * BST + ((lid >> 4) << 3)) * 2;
    uint32_t ast_off = (uint32_t)(ar * HSTRIDE + ac) * 2;
    uint32_t bst_off = (uint32_t)(kb * BST + cb) * 2;

    float4 pa0, pa1, pa2, pa3, pb0, pb1, pb2, pb3;
    {
        float4 zz = make_float4(0.f, 0.f, 0.f, 0.f);
        pa0 = aok ? *(const float4*)(ap)      : zz;
        pa1 = aok ? *(const float4*)(ap + 4)  : zz;
        pa2 = aok ? *(const float4*)(ap + 8)  : zz;
        pa3 = aok ? *(const float4*)(ap + 12) : zz;
        pb0 = bok0 ? *(const float4*)(bp)      : zz;
        pb1 = bok1 ? *(const float4*)(bp + 4)  : zz;
        pb2 = bok2 ? *(const float4*)(bp + 8)  : zz;
        pb3 = bok3 ? *(const float4*)(bp + 12) : zz;
    }

    for (int cc = 0; cc < L; cc++) {
        int s = cc & 1;
        uint32_t aHi = dm_u + (uint32_t)(s * 2 * A_BUF) * 2;
        uint32_t aLo = aHi + A_BUF * 2;
        uint32_t bB  = dm_u + (uint32_t)(4 * A_BUF + s * B_BUF) * 2;

        {
            unsigned h0, h1, h2, h3, h4, h5, h6, h7;
            unsigned l0, l1, l2, l3, l4, l5, l6, l7;
            split2h(pa0.x, pa0.y, h0, l0); split2h(pa0.z, pa0.w, h1, l1);
            split2h(pa1.x, pa1.y, h2, l2); split2h(pa1.z, pa1.w, h3, l3);
            split2h(pa2.x, pa2.y, h4, l4); split2h(pa2.z, pa2.w, h5, l5);
            split2h(pa3.x, pa3.y, h6, l6); split2h(pa3.z, pa3.w, h7, l7);
            asm volatile("st.shared.v4.b32 [%0], {%1,%2,%3,%4};" ::
                "r"(aHi + ast_off), "r"(h0), "r"(h1), "r"(h2), "r"(h3));
            asm volatile("st.shared.v4.b32 [%0], {%1,%2,%3,%4};" ::
                "r"(aHi + ast_off + 16), "r"(h4), "r"(h5), "r"(h6), "r"(h7));
            asm volatile("st.shared.v4.b32 [%0], {%1,%2,%3,%4};" ::
                "r"(aLo + ast_off), "r"(l0), "r"(l1), "r"(l2), "r"(l3));
            asm volatile("st.shared.v4.b32 [%0], {%1,%2,%3,%4};" ::
                "r"(aLo + ast_off + 16), "r"(l4), "r"(l5), "r"(l6), "r"(l7));
            h0 = packh(pb0.x, pb0.y); h1 = packh(pb0.z, pb0.w);
            h2 = packh(pb1.x, pb1.y); h3 = packh(pb1.z, pb1.w);
            h4 = packh(pb2.x, pb2.y); h5 = packh(pb2.z, pb2.w);
            h6 = packh(pb3.x, pb3.y); h7 = packh(pb3.z, pb3.w);
            asm volatile("st.shared.v4.b32 [%0], {%1,%2,%3,%4};" ::
                "r"(bB + bst_off), "r"(h0), "r"(h1), "r"(h2), "r"(h3));
            asm volatile("st.shared.v4.b32 [%0], {%1,%2,%3,%4};" ::
                "r"(bB + bst_off + 16), "r"(h4), "r"(h5), "r"(h6), "r"(h7));
        }

        if (cc + 1 < L) {
            int k0 = (cc + 1) * 32;
            const float* an = ap + k0;
            const float* bn = bp + (long long)k0 * ldb;
            float4 zz = make_float4(0.f, 0.f, 0.f, 0.f);
            pa0 = aok ? *(const float4*)(an)      : zz;
            pa1 = aok ? *(const float4*)(an + 4)  : zz;
            pa2 = aok ? *(const float4*)(an + 8)  : zz;
            pa3 = aok ? *(const float4*)(an + 12) : zz;
            pb0 = bok0 ? *(const float4*)(bn)      : zz;
            pb1 = bok1 ? *(const float4*)(bn + 4)  : zz;
            pb2 = bok2 ? *(const float4*)(bn + 8)  : zz;
            pb3 = bok3 ? *(const float4*)(bn + 12) : zz;
        }

        __syncthreads();

        #pragma unroll
        for (int kk = 0; kk < 2; kk++) {
            uint32_t ah[2][4], al[2][4], bh[4][4];
            #pragma unroll
            for (int mt = 0; mt < 2; mt++) {
                uint32_t ro = (uint32_t)((wm * 32 + mt * 16) * HSTRIDE) * 2 + a_off + kk * 32;
                ldm_x4(ah[mt], aHi + ro);
                ldm_x4(al[mt], aLo + ro);
            }
            #pragma unroll
            for (int nt2 = 0; nt2 < 4; nt2++) {
                uint32_t bo = (uint32_t)(kk * 16 * BST) * 2 + b_off
                            + (uint32_t)((wn * 64 + nt2 * 16) * 2);
                ldm_x4t(bh[nt2], bB + bo);
            }
            #pragma unroll
            for (int nt2 = 0; nt2 < 4; nt2++)
                #pragma unroll
                for (int mt = 0; mt < 2; mt++) {
                    mma16816h(acc[mt][nt2 * 2],     ah[mt], bh[nt2]);
                    mma16816h(acc[mt][nt2 * 2 + 1], ah[mt], bh[nt2] + 2);
                }
            #pragma unroll
            for (int nt2 = 0; nt2 < 4; nt2++)
                #pragma unroll
                for (int mt = 0; mt < 2; mt++) {
                    mma16816h(acc[mt][nt2 * 2],     al[mt], bh[nt2]);
                    mma16816h(acc[mt][nt2 * 2 + 1], al[mt], bh[nt2] + 2);
                }
        }
        __syncthreads();
    }

    int rr = lid >> 2, cc2 = (lid & 3) * 2;
    if (yg == nullptr) {
        #pragma unroll
        for (int mt = 0; mt < 2; mt++) {
            #pragma unroll
            for (int nt = 0; nt < 8; nt++) {
                int row = m0 + wm * 32 + mt * 16 + rr;
                int col = n0 + wn * 64 + nt * 8 + cc2;
                if (col < Nvalid) {
                    if (row < M)
                        *(float2*)(Cb + (long long)row * ldc + col) =
                            make_float2(acc[mt][nt][0], acc[mt][nt][1]);
                    if (row + 8 < M)
                        *(float2*)(Cb + (long long)(row + 8) * ldc + col) =
                            make_float2(acc[mt][nt][2], acc[mt][nt][3]);
                }
            }
        }
    } else {
        // fused Y epilogue (AX only: M=128, m0=0, Nvalid=DD, nsplit=1)
        #pragma unroll
        for (int mt = 0; mt < 2; mt++) {
            int rloc = wm * 32 + mt * 16 + rr;
            float sv0 = ys[batch * 128 + rloc];
            float sv1 = ys[batch * 128 + rloc + 8];
            long long yr0 = ((long long)(rloc >> 4) * LATROWS + batch * NL + (rloc & 15));
            int r2 = rloc + 8;
            long long yr1 = ((long long)(r2 >> 4) * LATROWS + batch * NL + (r2 & 15));
            #pragma unroll
            for (int nt = 0; nt < 8; nt++) {
                int col = n0 + wn * 64 + nt * 8 + cc2;
                float g0 = yg[col], g1 = yg[col + 1];
                *(float2*)(Cc + yr0 * DD + col) =
                    make_float2((acc[mt][nt][0] - sv0) * g0, (acc[mt][nt][1] - sv0) * g1);
                *(float2*)(Cc + yr1 * DD + col) =
                    make_float2((acc[mt][nt][2] - sv1) * g0, (acc[mt][nt][3] - sv1) * g1);
            }
        }
    }
}

// ---------------- generic split reduce + epilogue ----------------
__global__ void reduce_kernel(const float* __restrict__ parts, long long pstride, int nsplit,
                              float* __restrict__ out, long long n,
                              const float* __restrict__ addsrc, int add_mode,
                              const float* __restrict__ bias, int bias_period,
                              int do_gelu) {
    long long i = (long long)blockIdx.x * 256 + threadIdx.x;
    if (i >= n) return;
    float s = 0.f;
    for (int p = 0; p < nsplit; p++) s += parts[p * pstride + i];
    if (bias) s += bias[i % bias_period];
    if (do_gelu) s = 0.5f * s * (1.0f + erff(s * 0.70710678118654752f));
    if (add_mode == 1) s += addsrc[i];
    else if (add_mode == 2) {
        long long r = i >> 12;
        s += addsrc[((r & 15) << 12) + (i & 4095)];
    }
    out[i] = s;
}

// ---------------- qt_all (16 partials) ----------------
__global__ void qt_all_kernel(const float* __restrict__ qp, const float* __restrict__ wkv,
                              const float* __restrict__ g,
                              float* __restrict__ QTT, float* __restrict__ QG) {
    __shared__ float qs[NL * INNER];
    for (int i = threadIdx.x; i < NL * INNER; i += 256) {
        float s = 0.f;
        #pragma unroll
        for (int p = 0; p < 16; p++) s += qp[p * NL * INNER + i];
        qs[i] = s;
    }
    __syncthreads();
    int d = blockIdx.x * 32 + (threadIdx.x >> 3);
    int h = threadIdx.x & 7;
    const float* wrow = wkv + (long long)d * 1536 + h * DHH;
    float acc[NL];
    #pragma unroll
    for (int i = 0; i < NL; i++) acc[i] = 0.f;
    for (int dh = 0; dh < DHH; dh++) {
        float w = wrow[dh];
        #pragma unroll
        for (int i = 0; i < NL; i++) acc[i] = fmaf(qs[i * INNER + h * DHH + dh], w, acc[i]);
    }
    float gd = g[d];
    #pragma unroll
    for (int i = 0; i < NL; i++) {
        int ih = h * NL + i;
        QTT[(long long)d * 128 + ih] = acc[i];
        QG[(long long)d * 128 + ih] = acc[i] * gd;
    }
}

// ---------------- parallel u/v ----------------
__global__ void uv_part_kernel(const float* __restrict__ QTT, const float* __restrict__ g,
                               const float* __restrict__ b,
                               float* __restrict__ up, float* __restrict__ vp) {
    int ih = threadIdx.x;
    int c = blockIdx.x;
    float uu = 0.f, vv = 0.f;
    for (int d = c * 256; d < (c + 1) * 256; d++) {
        float t = QTT[(long long)d * 128 + ih];
        uu = fmaf(t, g[d], uu);
        vv = fmaf(t, b[d], vv);
    }
    up[c * 128 + ih] = uu;
    vp[c * 128 + ih] = vv;
}
__global__ void uv_comb_kernel(const float* __restrict__ up, const float* __restrict__ vp,
                               float* __restrict__ u, float* __restrict__ v) {
    int ih = threadIdx.x;
    float uu = 0.f, vv = 0.f;
    #pragma unroll
    for (int c = 0; c < 16; c++) { uu += up[c * 128 + ih]; vv += vp[c * 128 + ih]; }
    u[ih] = uu; v[ih] = vv;
}

// ---------------- parallel bv ----------------
__global__ void bv_part_kernel(const float* __restrict__ b, const float* __restrict__ wkv,
                               float* __restrict__ bvp) {
    int e = blockIdx.x * 128 + threadIdx.x;
    int c = blockIdx.y;
    float a = 0.f;
    for (int d = c * 256; d < (c + 1) * 256; d++)
        a = fmaf(b[d], wkv[(long long)d * 1536 + INNER + e], a);
    bvp[c * INNER + e] = a;
}
__global__ void bv_comb_kernel(const float* __restrict__ bvp, float* __restrict__ bv) {
    int e = blockIdx.x * 128 + threadIdx.x;
    float a = 0.f;
    #pragma unroll
    for (int c = 0; c < 16; c++) a += bvp[c * INNER + e];
    bv[e] = a;
}

// ---------------- attention softmax ----------------
__global__ void attn_kernel(const float* __restrict__ guid, const void* __restrict__ mask,
                            const float* __restrict__ S0, const float* __restrict__ mean,
                            const float* __restrict__ rstd,
                            const float* __restrict__ u, const float* __restrict__ v,
                            float* __restrict__ C, float* __restrict__ s_out) {
    extern __shared__ float sm[];
    float* sim = sm;
    float* rj  = sim + NL * NN;
    float* mj  = rj + NN;
    float* gu  = mj + NN;
    float* mk  = gu + NN;
    float* us  = mk + NN;
    float* vs  = us + NL;

    int bt = blockIdx.x >> 3;
    int h  = blockIdx.x & 7;
    int tid = threadIdx.x;
    int kind = g_mask_kind;

    for (int j = tid; j < NN; j += 256) {
        rj[j] = rstd[bt * NN + j];
        mj[j] = mean[bt * NN + j];
        gu[j] = guid[bt * NN + j];
        mk[j] = (kind == 1) ? (float)((const int*)mask)[bt * NN + j]
                            : (float)((const unsigned char*)mask)[bt * NN + j];
    }
    if (tid < NL) { us[tid] = u[h * NL + tid]; vs[tid] = v[h * NL + tid]; }
    __syncthreads();

    for (int idx = tid; idx < NL * NN; idx += 256) {
        int j = idx >> 4, i = idx & 15;
        float t = S0[((size_t)bt * NN + j) * 128 + h * NL + i];
        sim[i * NN + j] = ATTN_SCALE * (rj[j] * t - rj[j] * mj[j] * us[i] + vs[i]);
    }
    __syncthreads();

    int warp = tid >> 5, lane = tid & 31;
    for (int r = warp; r < NL; r += 8) {
        float* srow = sim + r * NN;
        float m0 = -FLT_MAX;
        for (int j = lane; j < NN; j += 32) m0 = fmaxf(m0, srow[j]);
        #pragma unroll
        for (int o = 16; o; o >>= 1) m0 = fmaxf(m0, __shfl_xor_sync(0xffffffffu, m0, o));

        float m1 = -FLT_MAX;
        for (int j = lane; j < NN; j += 32) {
            float s = srow[j] - m0;
            if (mk[j] != 0.f) s = -3.402823466e38f;
            s *= gu[j];
            srow[j] = s;
            m1 = fmaxf(m1, s);
        }
        #pragma unroll
        for (int o = 16; o; o >>= 1) m1 = fmaxf(m1, __shfl_xor_sync(0xffffffffu, m1, o));

        float sum = 0.f;
        for (int j = lane; j < NN; j += 32) {
            float e = expf(srow[j] - m1);
            srow[j] = e;
            sum += e;
        }
        #pragma unroll
        for (int o = 16; o; o >>= 1) sum += __shfl_xor_sync(0xffffffffu, sum, o);
        float inv = 1.f / sum;

        float sacc = 0.f;
        float* crow = C + ((size_t)bt * 128 + h * NL + r) * NN;
        for (int j = lane; j < NN; j += 32) {
            float a = srow[j] * inv;
            float c = a * rj[j];
            crow[j] = c;
            sacc = fmaf(c, mj[j], sacc);
        }
        #pragma unroll
        for (int o = 16; o; o >>= 1) sacc += __shfl_xor_sync(0xffffffffu, sacc, o);
        if (lane == 0) s_out[bt * 128 + h * NL + r] = sacc;
    }
}

// ---------------- launch ----------------
extern "C" void kernel_launch(void* const* d_in, const int* in_sizes, int n_in,
                              void* d_out, int out_size) {
    const float* x       = (const float*)d_in[0];
    const float* guid    = (const float*)d_in[1];
    const void*  mask    = d_in[2];
    const float* latents = (const float*)d_in[3];
    const float* nm_g    = (const float*)d_in[4];
    const float* nm_b    = (const float*)d_in[5];
    const float* nl_g    = (const float*)d_in[6];
    const float* nl_b    = (const float*)d_in[7];
    const float* wq      = (const float*)d_in[8];
    const float* wkv     = (const float*)d_in[9];
    const float* wout    = (const float*)d_in[10];
    const float* ff_g    = (const float*)d_in[11];
    const float* ff_b    = (const float*)d_in[12];
    const float* w1      = (const float*)d_in[13];
    const float* w2      = (const float*)d_in[14];
    const float* fn_g    = (const float*)d_in[15];
    const float* fn_b    = (const float*)d_in[16];
    float* out = (float*)d_out;

    float *p_mean, *p_rstd, *p_ql, *p_qp, *p_QTT, *p_QG, *p_u, *p_v, *p_bv;
    float *p_up, *p_vp, *p_bvp;
    float *p_S0, *p_C, *p_s, *p_Y, *p_Vp, *p_attnv, *p_woutp;
    float *p_lat1, *p_ffln, *p_ff1p, *p_h1, *p_ff2p, *p_lat2;
    cudaGetSymbolAddress((void**)&p_mean, g_mean);
    cudaGetSymbolAddress((void**)&p_rstd, g_rstd);
    cudaGetSymbolAddress((void**)&p_ql, g_ql);
    cudaGetSymbolAddress((void**)&p_qp, g_qp);
    cudaGetSymbolAddress((void**)&p_QTT, g_QTT);
    cudaGetSymbolAddress((void**)&p_QG, g_QG);
    cudaGetSymbolAddress((void**)&p_u, g_u);
    cudaGetSymbolAddress((void**)&p_v, g_v);
    cudaGetSymbolAddress((void**)&p_bv, g_bv);
    cudaGetSymbolAddress((void**)&p_up, g_up);
    cudaGetSymbolAddress((void**)&p_vp, g_vp);
    cudaGetSymbolAddress((void**)&p_bvp, g_bvp);
    cudaGetSymbolAddress((void**)&p_S0, g_S0);
    cudaGetSymbolAddress((void**)&p_C, g_C);
    cudaGetSymbolAddress((void**)&p_s, g_s);
    cudaGetSymbolAddress((void**)&p_Y, g_Y);
    cudaGetSymbolAddress((void**)&p_Vp, g_Vp);
    cudaGetSymbolAddress((void**)&p_attnv, g_attnv);
    cudaGetSymbolAddress((void**)&p_woutp, g_woutp);
    cudaGetSymbolAddress((void**)&p_lat1, g_lat1);
    cudaGetSymbolAddress((void**)&p_ffln, g_ffln);
    cudaGetSymbolAddress((void**)&p_ff1p, g_ff1p);
    cudaGetSymbolAddress((void**)&p_h1, g_h1);
    cudaGetSymbolAddress((void**)&p_ff2p, g_ff2p);
    cudaGetSymbolAddress((void**)&p_lat2, g_lat2);

    cudaFuncSetAttribute(hmma3, cudaFuncAttributeMaxDynamicSharedMemorySize, HSMEM3);
    cudaFuncSetAttribute(hmma2, cudaFuncAttributeMaxDynamicSharedMemorySize, HSMEM2);

    // #1 ql = LN(latents)
    ln_rows_kernel<<<NL, 256>>>(latents, p_ql, nl_g, nl_b);
    // #2 qp = ql @ wq partials (split-K 16)
    hmma3<<<dim3(6, 1, 16), 256, HSMEM3>>>(p_ql, DD, 0, wq, INNER, 0,
                                           p_qp, INNER, 0, NL * INNER,
                                           NL, INNER, DD, 16, nullptr, nullptr);
    // #3 qt_all
    qt_all_kernel<<<DD / 32, 256>>>(p_qp, wkv, nm_g, p_QTT, p_QG);

    // #4 S0 = x @ QG + fused x row stats
    hmma3<<<dim3(1, XROWS / 128, 1), 256, HSMEM3>>>(x, DD, 0, p_QG, 128, 0,
                                                    p_S0, 128, 0, 0,
                                                    XROWS, 128, DD, 1, p_mean, p_rstd);

    // u/v (parallel), bv (parallel), mask-kind
    uv_part_kernel<<<16, 128>>>(p_QTT, nm_g, nm_b, p_up, p_vp);
    uv_comb_kernel<<<1, 128>>>(p_up, p_vp, p_u, p_v);
    bv_part_kernel<<<dim3(INNER / 128, 16), 128>>>(nm_b, wkv, p_bvp);
    bv_comb_kernel<<<INNER / 128, 128>>>(p_bvp, p_bv);
    detect_mask_kernel<<<1, 256>>>((const unsigned int*)mask);

    // softmax -> C, s
    {
        int smemb = (NL * NN + 4 * NN + 2 * NL) * (int)sizeof(float);
        cudaFuncSetAttribute(attn_kernel, cudaFuncAttributeMaxDynamicSharedMemorySize, smemb);
        attn_kernel<<<BT * HH, 256, smemb>>>(guid, mask, p_S0, p_mean, p_rstd,
                                             p_u, p_v, p_C, p_s);
    }

    // AX[bt] = C[bt] @ x[bt] with fused Y epilogue
    hmma2<<<dim3(DD / 128, 1, BT), 256, HSMEM2>>>(
        p_C, NN, (long long)128 * NN, x, DD, (long long)NN * DD,
        p_Y, DD, 0, 0, 128, DD, NN, 1, nm_g, p_s);

    // attnV (split-K 16)
    hmma2<<<dim3(1, 2, HH * 16), 256, HSMEM2>>>(
        p_Y, DD, (long long)LATROWS * DD, wkv + INNER, 1536, 96,
        p_Vp, INNER, 96, (long long)LATROWS * INNER, LATROWS, 96, DD, 16,
        nullptr, nullptr);
    reduce_kernel<<<(LATROWS * INNER + 255) / 256, 256>>>(
        p_Vp, (long long)LATROWS * INNER, 16, p_attnv, LATROWS * INNER,
        nullptr, 0, p_bv, INNER, 0);

    // lat1 = attnv @ wout + latents (split-K 4)
    hmma2<<<dim3(DD / 128, 2, 4), 256, HSMEM2>>>(
        p_attnv, INNER, 0, wout, DD, 0,
        p_woutp, DD, 0, (long long)LATROWS * DD, LATROWS, DD, INNER, 4,
        nullptr, nullptr);
    reduce_kernel<<<(LATROWS * DD + 255) / 256, 256>>>(
        p_woutp, (long long)LATROWS * DD, 4, p_lat1, LATROWS * DD,
        latents, 2, nullptr, 1, 0);

    // FF
    ln_rows_kernel<<<LATROWS, 256>>>(p_lat1, p_ffln, ff_g, ff_b);
    hmma2<<<dim3(FF / 128, 2, 2), 256, HSMEM2>>>(
        p_ffln, DD, 0, w1, FF, 0,
        p_ff1p, FF, 0, (long long)LATROWS * FF, LATROWS, FF, DD, 2,
        nullptr, nullptr);
    reduce_kernel<<<((long long)LATROWS * FF + 255) / 256, 256>>>(
        p_ff1p, (long long)LATROWS * FF, 2, p_h1, (long long)LATROWS * FF,
        nullptr, 0, nullptr, 1, 1);
    hmma2<<<dim3(DD / 128, 2, 4), 256, HSMEM2>>>(
        p_h1, FF, 0, w2, DD, 0,
        p_ff2p, DD, 0, (long long)LATROWS * DD, LATROWS, DD, FF, 4,
        nullptr, nullptr);
    reduce_kernel<<<(LATROWS * DD + 255) / 256, 256>>>(
        p_ff2p, (long long)LATROWS * DD, 4, p_lat2, LATROWS * DD,
        p_lat1, 1, nullptr, 1, 0);

    // final LN
    ln_rows_kernel<<<LATROWS, 256>>>(p_lat2, out, fn_g, fn_b);
}

// round 17
// speedup vs baseline: 1.1698x; 1.0506x over previous
#include <cuda_runtime.h>
#include <cuda_bf16.h>
#include <cuda_fp16.h>
#include <cfloat>
#include <math.h>
#include <stdint.h>

// ---------------- problem constants ----------------
#define NN 1792
#define DD 4096
#define HH 8
#define DHH 96
#define INNER 768
#define NL 16
#define FF 8192
#define BT 16
#define XROWS 28672
#define LATROWS 256
#define EPS 1e-5f
#define ATTN_SCALE 0.10206207261596577f

// ---------------- scratch ----------------
__device__ float g_mean[XROWS];
__device__ float g_rstd[XROWS];
__device__ int   g_mask_kind;

__device__ float g_ql[NL * DD];
__device__ float g_qp[16 * NL * INNER];

__device__ float g_QTT[DD * 128];
__device__ float g_QG[DD * 128];
__device__ float g_u[128];
__device__ float g_v[128];
__device__ float g_bv[INNER];
__device__ float g_up[16 * 128];
__device__ float g_vp[16 * 128];
__device__ float g_bvp[16 * INNER];

__device__ float g_S0[(size_t)XROWS * 128];
__device__ float g_C[(size_t)BT * 128 * NN];
__device__ float g_s[BT * 128];
__device__ float g_Y[(size_t)HH * LATROWS * DD];

__device__ float g_Vp[16 * (size_t)LATROWS * INNER];
__device__ float g_attnv[LATROWS * INNER];
__device__ float g_woutp[4 * (size_t)LATROWS * DD];
__device__ float g_lat1[LATROWS * DD];
__device__ float g_ffln[LATROWS * DD];
__device__ float g_ff1p[2 * (size_t)LATROWS * FF];
__device__ float g_h1[(size_t)LATROWS * FF];
__device__ float g_ff2p[4 * (size_t)LATROWS * DD];
__device__ float g_lat2[LATROWS * DD];

// ---------------- helpers ----------------
__device__ __forceinline__ uint32_t smem_u32(const void* p) {
    uint32_t a;
    asm("{ .reg .u64 t; cvta.to.shared.u64 t, %1; cvt.u32.u64 %0, t; }" : "=r"(a) : "l"(p));
    return a;
}
__device__ __forceinline__ void ldm_x4(uint32_t* r, uint32_t addr) {
    asm volatile("ldmatrix.sync.aligned.m8n8.x4.shared.b16 {%0,%1,%2,%3}, [%4];"
                 : "=r"(r[0]), "=r"(r[1]), "=r"(r[2]), "=r"(r[3]) : "r"(addr));
}
__device__ __forceinline__ void ldm_x4t(uint32_t* r, uint32_t addr) {
    asm volatile("ldmatrix.sync.aligned.m8n8.x4.trans.shared.b16 {%0,%1,%2,%3}, [%4];"
                 : "=r"(r[0]), "=r"(r[1]), "=r"(r[2]), "=r"(r[3]) : "r"(addr));
}
__device__ __forceinline__ void mma16816(float* c, const uint32_t* a, const uint32_t* b) {
    asm volatile(
        "mma.sync.aligned.m16n8k16.row.col.f32.bf16.bf16.f32 "
        "{%0,%1,%2,%3}, {%4,%5,%6,%7}, {%8,%9}, {%0,%1,%2,%3};"
        : "+f"(c[0]), "+f"(c[1]), "+f"(c[2]), "+f"(c[3])
        : "r"(a[0]), "r"(a[1]), "r"(a[2]), "r"(a[3]), "r"(b[0]), "r"(b[1]));
}
__device__ __forceinline__ void mma16816h(float* c, const uint32_t* a, const uint32_t* b) {
    asm volatile(
        "mma.sync.aligned.m16n8k16.row.col.f32.f16.f16.f32 "
        "{%0,%1,%2,%3}, {%4,%5,%6,%7}, {%8,%9}, {%0,%1,%2,%3};"
        : "+f"(c[0]), "+f"(c[1]), "+f"(c[2]), "+f"(c[3])
        : "r"(a[0]), "r"(a[1]), "r"(a[2]), "r"(a[3]), "r"(b[0]), "r"(b[1]));
}
__device__ __forceinline__ void split2(float x, float y, unsigned& h, unsigned& l) {
    __nv_bfloat162 hh = __floats2bfloat162_rn(x, y);
    float r0 = x - __bfloat162float(__low2bfloat16(hh));
    float r1 = y - __bfloat162float(__high2bfloat16(hh));
    __nv_bfloat162 ll = __floats2bfloat162_rn(r0, r1);
    h = *reinterpret_cast<unsigned*>(&hh);
    l = *reinterpret_cast<unsigned*>(&ll);
}
__device__ __forceinline__ void split2h(float x, float y, unsigned& h, unsigned& l) {
    __half2 hh = __floats2half2_rn(x, y);
    float r0 = x - __half2float(__low2half(hh));
    float r1 = y - __half2float(__high2half(hh));
    __half2 ll = __floats2half2_rn(r0, r1);
    h = *reinterpret_cast<unsigned*>(&hh);
    l = *reinterpret_cast<unsigned*>(&ll);
}
__device__ __forceinline__ unsigned packh(float x, float y) {
    __half2 hh = __floats2half2_rn(x, y);
    return *reinterpret_cast<unsigned*>(&hh);
}

// ---------------- mask kind detection ----------------
__global__ void detect_mask_kernel(const unsigned int* __restrict__ m) {
    __shared__ unsigned int sh[8];
    unsigned int orv = 0;
    for (int i = threadIdx.x; i < XROWS / 4; i += 256) orv |= m[i];
    #pragma unroll
    for (int o = 16; o; o >>= 1) orv |= __shfl_xor_sync(0xffffffffu, orv, o);
    int w = threadIdx.x >> 5;
    if ((threadIdx.x & 31) == 0) sh[w] = orv;
    __syncthreads();
    if (threadIdx.x == 0) {
        unsigned int t = 0;
        #pragma unroll
        for (int i = 0; i < 8; i++) t |= sh[i];
        g_mask_kind = (t <= 1u) ? 1 : 0;
    }
}

// ---------------- layernorm ----------------
__global__ void ln_rows_kernel(const float* __restrict__ in, float* __restrict__ out,
                               const float* __restrict__ g, const float* __restrict__ b) {
    int row = blockIdx.x;
    const float* xr = in + (size_t)row * DD;
    float s = 0.f, q = 0.f;
    for (int i = threadIdx.x; i < DD; i += blockDim.x) { float v = xr[i]; s += v; q += v * v; }
    #pragma unroll
    for (int o = 16; o; o >>= 1) {
        s += __shfl_xor_sync(0xffffffffu, s, o);
        q += __shfl_xor_sync(0xffffffffu, q, o);
    }
    __shared__ float sh_s[8], sh_q[8];
    __shared__ float m_sh, r_sh;
    int w = threadIdx.x >> 5, l = threadIdx.x & 31;
    if (l == 0) { sh_s[w] = s; sh_q[w] = q; }
    __syncthreads();
    if (threadIdx.x == 0) {
        float S = 0.f, Q = 0.f;
        #pragma unroll
        for (int i = 0; i < 8; i++) { S += sh_s[i]; Q += sh_q[i]; }
        float m = S / (float)DD;
        m_sh = m;
        r_sh = rsqrtf(Q / (float)DD - m * m + EPS);
    }
    __syncthreads();
    float m = m_sh, r = r_sh;
    for (int i = threadIdx.x; i < DD; i += blockDim.x)
        out[(size_t)row * DD + i] = (xr[i] - m) * r * g[i] + b[i];
}

// ================= hmma3: bf16 3-term (R8-proven) =================
#define HSTRIDE 40
#define BST 136
#define A_BUF 5120
#define B_BUF 4352
#define HSMEM3 ((4 * A_BUF + 4 * B_BUF) * 2)
__global__ void __launch_bounds__(256, 1)
hmma3(const float* __restrict__ A, long long lda, long long abatch,
      const float* __restrict__ B, long long ldb, long long bbatch,
      float* __restrict__ Cc, long long ldc, long long cbatch, long long csplit,
      int M, int Nvalid, int Ktot, int nsplit) {
    extern __shared__ __nv_bfloat16 dynsm[];
    uint32_t dm_u = smem_u32(dynsm);

    int tid = threadIdx.x, wid = tid >> 5, lid = tid & 31;
    int z = blockIdx.z;
    int batch = z / nsplit, split = z - batch * nsplit;
    int n0 = blockIdx.x * 128, m0 = blockIdx.y * 128;
    int Kchunk = Ktot / nsplit, kbeg = split * Kchunk;
    int L = Kchunk / 32;

    const float* Ab = A + abatch * batch;
    const float* Bb = B + bbatch * batch;
    float* Cb = Cc + cbatch * batch + csplit * split;

    int ar = tid >> 1, ac = (tid & 1) * 16;
    bool aok = (m0 + ar) < M;
    const float* ap = Ab + (long long)(m0 + ar) * lda + kbeg + ac;
    int kb = tid >> 3, cb = (tid & 7) * 16;
    const float* bp = Bb + (long long)(kbeg + kb) * ldb + n0 + cb;
    bool bok0 = (n0 + cb) < Nvalid, bok1 = (n0 + cb + 4) < Nvalid;
    bool bok2 = (n0 + cb + 8) < Nvalid, bok3 = (n0 + cb + 12) < Nvalid;

    int wm = wid >> 1, wn = wid & 1;
    float acc[2][8][4];
    #pragma unroll
    for (int a1 = 0; a1 < 2; a1++)
        #pragma unroll
        for (int b1 = 0; b1 < 8; b1++)
            #pragma unroll
            for (int c1 = 0; c1 < 4; c1++) acc[a1][b1][c1] = 0.f;

    uint32_t a_off = (uint32_t)(((lid & 15)) * HSTRIDE + (lid >> 4) * 8) * 2;
    uint32_t b_off = (uint32_t)(((lid & 15)) * BST + ((lid >> 4) << 3)) * 2;
    uint32_t ast_off = (uint32_t)(ar * HSTRIDE + ac) * 2;
    uint32_t bst_off = (uint32_t)(kb * BST + cb) * 2;

    float4 pa0, pa1, pa2, pa3, pb0, pb1, pb2, pb3;
    {
        float4 zz = make_float4(0.f, 0.f, 0.f, 0.f);
        pa0 = aok ? *(const float4*)(ap)      : zz;
        pa1 = aok ? *(const float4*)(ap + 4)  : zz;
        pa2 = aok ? *(const float4*)(ap + 8)  : zz;
        pa3 = aok ? *(const float4*)(ap + 12) : zz;
        pb0 = bok0 ? *(const float4*)(bp)      : zz;
        pb1 = bok1 ? *(const float4*)(bp + 4)  : zz;
        pb2 = bok2 ? *(const float4*)(bp + 8)  : zz;
        pb3 = bok3 ? *(const float4*)(bp + 12) : zz;
    }

    for (int cc = 0; cc < L; cc++) {
        int s = cc & 1;
        uint32_t aHi = dm_u + (uint32_t)(s * 2 * A_BUF) * 2;
        uint32_t aLo = aHi + A_BUF * 2;
        uint32_t bHi = dm_u + (uint32_t)(4 * A_BUF + s * 2 * B_BUF) * 2;
        uint32_t bLo = bHi + B_BUF * 2;

        {
            unsigned h0, h1, h2, h3, h4, h5, h6, h7;
            unsigned l0, l1, l2, l3, l4, l5, l6, l7;
            split2(pa0.x, pa0.y, h0, l0); split2(pa0.z, pa0.w, h1, l1);
            split2(pa1.x, pa1.y, h2, l2); split2(pa1.z, pa1.w, h3, l3);
            split2(pa2.x, pa2.y, h4, l4); split2(pa2.z, pa2.w, h5, l5);
            split2(pa3.x, pa3.y, h6, l6); split2(pa3.z, pa3.w, h7, l7);
            asm volatile("st.shared.v4.b32 [%0], {%1,%2,%3,%4};" ::
                "r"(aHi + ast_off), "r"(h0), "r"(h1), "r"(h2), "r"(h3));
            asm volatile("st.shared.v4.b32 [%0], {%1,%2,%3,%4};" ::
                "r"(aHi + ast_off + 16), "r"(h4), "r"(h5), "r"(h6), "r"(h7));
            asm volatile("st.shared.v4.b32 [%0], {%1,%2,%3,%4};" ::
                "r"(aLo + ast_off), "r"(l0), "r"(l1), "r"(l2), "r"(l3));
            asm volatile("st.shared.v4.b32 [%0], {%1,%2,%3,%4};" ::
                "r"(aLo + ast_off + 16), "r"(l4), "r"(l5), "r"(l6), "r"(l7));
            split2(pb0.x, pb0.y, h0, l0); split2(pb0.z, pb0.w, h1, l1);
            split2(pb1.x, pb1.y, h2, l2); split2(pb1.z, pb1.w, h3, l3);
            split2(pb2.x, pb2.y, h4, l4); split2(pb2.z, pb2.w, h5, l5);
            split2(pb3.x, pb3.y, h6, l6); split2(pb3.z, pb3.w, h7, l7);
            asm volatile("st.shared.v4.b32 [%0], {%1,%2,%3,%4};" ::
                "r"(bHi + bst_off), "r"(h0), "r"(h1), "r"(h2), "r"(h3));
            asm volatile("st.shared.v4.b32 [%0], {%1,%2,%3,%4};" ::
                "r"(bHi + bst_off + 16), "r"(h4), "r"(h5), "r"(h6), "r"(h7));
            asm volatile("st.shared.v4.b32 [%0], {%1,%2,%3,%4};" ::
                "r"(bLo + bst_off), "r"(l0), "r"(l1), "r"(l2), "r"(l3));
            asm volatile("st.shared.v4.b32 [%0], {%1,%2,%3,%4};" ::
                "r"(bLo + bst_off + 16), "r"(l4), "r"(l5), "r"(l6), "r"(l7));
        }

        if (cc + 1 < L) {
            int k0 = (cc + 1) * 32;
            const float* an = ap + k0;
            const float* bn = bp + (long long)k0 * ldb;
            float4 zz = make_float4(0.f, 0.f, 0.f, 0.f);
            pa0 = aok ? *(const float4*)(an)      : zz;
            pa1 = aok ? *(const float4*)(an + 4)  : zz;
            pa2 = aok ? *(const float4*)(an + 8)  : zz;
            pa3 = aok ? *(const float4*)(an + 12) : zz;
            pb0 = bok0 ? *(const float4*)(bn)      : zz;
            pb1 = bok1 ? *(const float4*)(bn + 4)  : zz;
            pb2 = bok2 ? *(const float4*)(bn + 8)  : zz;
            pb3 = bok3 ? *(const float4*)(bn + 12) : zz;
        }

        __syncthreads();

        #pragma unroll
        for (int kk = 0; kk < 2; kk++) {
            uint32_t ah[2][4], al[2][4], bh[4][4], bl[4][4];
            #pragma unroll
            for (int mt = 0; mt < 2; mt++) {
                uint32_t ro = (uint32_t)((wm * 32 + mt * 16) * HSTRIDE) * 2 + a_off + kk * 32;
                ldm_x4(ah[mt], aHi + ro);
                ldm_x4(al[mt], aLo + ro);
            }
            #pragma unroll
            for (int nt2 = 0; nt2 < 4; nt2++) {
                uint32_t bo = (uint32_t)(kk * 16 * BST) * 2 + b_off
                            + (uint32_t)((wn * 64 + nt2 * 16) * 2);
                ldm_x4t(bh[nt2], bHi + bo);
                ldm_x4t(bl[nt2], bLo + bo);
            }
            #pragma unroll
            for (int nt2 = 0; nt2 < 4; nt2++)
                #pragma unroll
                for (int mt = 0; mt < 2; mt++) {
                    mma16816(acc[mt][nt2 * 2],     ah[mt], bh[nt2]);
                    mma16816(acc[mt][nt2 * 2 + 1], ah[mt], bh[nt2] + 2);
                }
            #pragma unroll
            for (int nt2 = 0; nt2 < 4; nt2++)
                #pragma unroll
                for (int mt = 0; mt < 2; mt++) {
                    mma16816(acc[mt][nt2 * 2],     ah[mt], bl[nt2]);
                    mma16816(acc[mt][nt2 * 2 + 1], ah[mt], bl[nt2] + 2);
                }
            #pragma unroll
            for (int nt2 = 0; nt2 < 4; nt2++)
                #pragma unroll
                for (int mt = 0; mt < 2; mt++) {
                    mma16816(acc[mt][nt2 * 2],     al[mt], bh[nt2]);
                    mma16816(acc[mt][nt2 * 2 + 1], al[mt], bh[nt2] + 2);
                }
        }
        __syncthreads();
    }

    int rr = lid >> 2, cc2 = (lid & 3) * 2;
    #pragma unroll
    for (int mt = 0; mt < 2; mt++) {
        #pragma unroll
        for (int nt = 0; nt < 8; nt++) {
            int row = m0 + wm * 32 + mt * 16 + rr;
            int col = n0 + wn * 64 + nt * 8 + cc2;
            if (col < Nvalid) {
                if (row < M)
                    *(float2*)(Cb + (long long)row * ldc + col) =
                        make_float2(acc[mt][nt][0], acc[mt][nt][1]);
                if (row + 8 < M)
                    *(float2*)(Cb + (long long)(row + 8) * ldc + col) =
                        make_float2(acc[mt][nt][2], acc[mt][nt][3]);
            }
        }
    }
}

// ==== hmma2: fp16 2-term + optional fused Y epilogue + optional row stats ====
#define HSMEM2 ((4 * A_BUF + 2 * B_BUF) * 2)
__global__ void __launch_bounds__(256, 1)
hmma2(const float* __restrict__ A, long long lda, long long abatch,
      const float* __restrict__ B, long long ldb, long long bbatch,
      float* __restrict__ Cc, long long ldc, long long cbatch, long long csplit,
      int M, int Nvalid, int Ktot, int nsplit,
      const float* __restrict__ yg, const float* __restrict__ ys,
      float* __restrict__ stats_mean, float* __restrict__ stats_rstd) {
    extern __shared__ __nv_bfloat16 dynsm[];
    uint32_t dm_u = smem_u32(dynsm);

    int tid = threadIdx.x, wid = tid >> 5, lid = tid & 31;
    int z = blockIdx.z;
    int batch = z / nsplit, split = z - batch * nsplit;
    int n0 = blockIdx.x * 128, m0 = blockIdx.y * 128;
    int Kchunk = Ktot / nsplit, kbeg = split * Kchunk;
    int L = Kchunk / 32;

    const float* Ab = A + abatch * batch;
    const float* Bb = B + bbatch * batch;
    float* Cb = Cc + cbatch * batch + csplit * split;

    int ar = tid >> 1, ac = (tid & 1) * 16;
    bool aok = (m0 + ar) < M;
    const float* ap = Ab + (long long)(m0 + ar) * lda + kbeg + ac;
    int kb = tid >> 3, cb = (tid & 7) * 16;
    const float* bp = Bb + (long long)(kbeg + kb) * ldb + n0 + cb;
    bool bok0 = (n0 + cb) < Nvalid, bok1 = (n0 + cb + 4) < Nvalid;
    bool bok2 = (n0 + cb + 8) < Nvalid, bok3 = (n0 + cb + 12) < Nvalid;

    int wm = wid >> 1, wn = wid & 1;
    float acc[2][8][4];
    #pragma unroll
    for (int a1 = 0; a1 < 2; a1++)
        #pragma unroll
        for (int b1 = 0; b1 < 8; b1++)
            #pragma unroll
            for (int c1 = 0; c1 < 4; c1++) acc[a1][b1][c1] = 0.f;

    uint32_t a_off = (uint32_t)(((lid & 15)) * HSTRIDE + (lid >> 4) * 8) * 2;
    uint32_t b_off = (uint32_t)(((lid & 15)) * BST + ((lid >> 4) << 3)) * 2;
    uint32_t ast_off = (uint32_t)(ar * HSTRIDE + ac) * 2;
    uint32_t bst_off = (uint32_t)(kb * BST + cb) * 2;

    bool do_stats = (stats_mean != nullptr);
    float ssum = 0.f, sqsum = 0.f;

    float4 pa0, pa1, pa2, pa3, pb0, pb1, pb2, pb3;
    {
        float4 zz = make_float4(0.f, 0.f, 0.f, 0.f);
        pa0 = aok ? *(const float4*)(ap)      : zz;
        pa1 = aok ? *(const float4*)(ap + 4)  : zz;
        pa2 = aok ? *(const float4*)(ap + 8)  : zz;
        pa3 = aok ? *(const float4*)(ap + 12) : zz;
        pb0 = bok0 ? *(const float4*)(bp)      : zz;
        pb1 = bok1 ? *(const float4*)(bp + 4)  : zz;
        pb2 = bok2 ? *(const float4*)(bp + 8)  : zz;
        pb3 = bok3 ? *(const float4*)(bp + 12) : zz;
    }

    for (int cc = 0; cc < L; cc++) {
        int s = cc & 1;
        uint32_t aHi = dm_u + (uint32_t)(s * 2 * A_BUF) * 2;
        uint32_t aLo = aHi + A_BUF * 2;
        uint32_t bB  = dm_u + (uint32_t)(4 * A_BUF + s * B_BUF) * 2;

        {
            if (do_stats) {
                ssum += pa0.x + pa0.y + pa0.z + pa0.w + pa1.x + pa1.y + pa1.z + pa1.w
                      + pa2.x + pa2.y + pa2.z + pa2.w + pa3.x + pa3.y + pa3.z + pa3.w;
                sqsum += pa0.x*pa0.x + pa0.y*pa0.y + pa0.z*pa0.z + pa0.w*pa0.w
                       + pa1.x*pa1.x + pa1.y*pa1.y + pa1.z*pa1.z + pa1.w*pa1.w
                       + pa2.x*pa2.x + pa2.y*pa2.y + pa2.z*pa2.z + pa2.w*pa2.w
                       + pa3.x*pa3.x + pa3.y*pa3.y + pa3.z*pa3.z + pa3.w*pa3.w;
            }
            unsigned h0, h1, h2, h3, h4, h5, h6, h7;
            unsigned l0, l1, l2, l3, l4, l5, l6, l7;
            split2h(pa0.x, pa0.y, h0, l0); split2h(pa0.z, pa0.w, h1, l1);
            split2h(pa1.x, pa1.y, h2, l2); split2h(pa1.z, pa1.w, h3, l3);
            split2h(pa2.x, pa2.y, h4, l4); split2h(pa2.z, pa2.w, h5, l5);
            split2h(pa3.x, pa3.y, h6, l6); split2h(pa3.z, pa3.w, h7, l7);
            asm volatile("st.shared.v4.b32 [%0], {%1,%2,%3,%4};" ::
                "r"(aHi + ast_off), "r"(h0), "r"(h1), "r"(h2), "r"(h3));
            asm volatile("st.shared.v4.b32 [%0], {%1,%2,%3,%4};" ::
                "r"(aHi + ast_off + 16), "r"(h4), "r"(h5), "r"(h6), "r"(h7));
            asm volatile("st.shared.v4.b32 [%0], {%1,%2,%3,%4};" ::
                "r"(aLo + ast_off), "r"(l0), "r"(l1), "r"(l2), "r"(l3));
            asm volatile("st.shared.v4.b32 [%0], {%1,%2,%3,%4};" ::
                "r"(aLo + ast_off + 16), "r"(l4), "r"(l5), "r"(l6), "r"(l7));
            h0 = packh(pb0.x, pb0.y); h1 = packh(pb0.z, pb0.w);
            h2 = packh(pb1.x, pb1.y); h3 = packh(pb1.z, pb1.w);
            h4 = packh(pb2.x, pb2.y); h5 = packh(pb2.z, pb2.w);
            h6 = packh(pb3.x, pb3.y); h7 = packh(pb3.z, pb3.w);
            asm volatile("st.shared.v4.b32 [%0], {%1,%2,%3,%4};" ::
                "r"(bB + bst_off), "r"(h0), "r"(h1), "r"(h2), "r"(h3));
            asm volatile("st.shared.v4.b32 [%0], {%1,%2,%3,%4};" ::
                "r"(bB + bst_off + 16), "r"(h4), "r"(h5), "r"(h6), "r"(h7));
        }

        if (cc + 1 < L) {
            int k0 = (cc + 1) * 32;
            const float* an = ap + k0;
            const float* bn = bp + (long long)k0 * ldb;
            float4 zz = make_float4(0.f, 0.f, 0.f, 0.f);
            pa0 = aok ? *(const float4*)(an)      : zz;
            pa1 = aok ? *(const float4*)(an + 4)  : zz;
            pa2 = aok ? *(const float4*)(an + 8)  : zz;
            pa3 = aok ? *(const float4*)(an + 12) : zz;
            pb0 = bok0 ? *(const float4*)(bn)      : zz;
            pb1 = bok1 ? *(const float4*)(bn + 4)  : zz;
            pb2 = bok2 ? *(const float4*)(bn + 8)  : zz;
            pb3 = bok3 ? *(const float4*)(bn + 12) : zz;
        }

        __syncthreads();

        #pragma unroll
        for (int kk = 0; kk < 2; kk++) {
            uint32_t ah[2][4], al[2][4], bh[4][4];
            #pragma unroll
            for (int mt = 0; mt < 2; mt++) {
                uint32_t ro = (uint32_t)((wm * 32 + mt * 16) * HSTRIDE) * 2 + a_off + kk * 32;
                ldm_x4(ah[mt], aHi + ro);
                ldm_x4(al[mt], aLo + ro);
            }
            #pragma unroll
            for (int nt2 = 0; nt2 < 4; nt2++) {
                uint32_t bo = (uint32_t)(kk * 16 * BST) * 2 + b_off
                            + (uint32_t)((wn * 64 + nt2 * 16) * 2);
                ldm_x4t(bh[nt2], bB + bo);
            }
            #pragma unroll
            for (int nt2 = 0; nt2 < 4; nt2++)
                #pragma unroll
                for (int mt = 0; mt < 2; mt++) {
                    mma16816h(acc[mt][nt2 * 2],     ah[mt], bh[nt2]);
                    mma16816h(acc[mt][nt2 * 2 + 1], ah[mt], bh[nt2] + 2);
                }
            #pragma unroll
            for (int nt2 = 0; nt2 < 4; nt2++)
                #pragma unroll
                for (int mt = 0; mt < 2; mt++) {
                    mma16816h(acc[mt][nt2 * 2],     al[mt], bh[nt2]);
                    mma16816h(acc[mt][nt2 * 2 + 1], al[mt], bh[nt2] + 2);
                }
        }
        __syncthreads();
    }

    if (do_stats && aok) {
        float s2 = ssum + __shfl_xor_sync(0xffffffffu, ssum, 1);
        float q2 = sqsum + __shfl_xor_sync(0xffffffffu, sqsum, 1);
        if ((tid & 1) == 0) {
            float m = s2 / (float)DD;
            stats_mean[m0 + ar] = m;
            stats_rstd[m0 + ar] = rsqrtf(q2 / (float)DD - m * m + EPS);
        }
    }

    int rr = lid >> 2, cc2 = (lid & 3) * 2;
    if (yg == nullptr) {
        #pragma unroll
        for (int mt = 0; mt < 2; mt++) {
            #pragma unroll
            for (int nt = 0; nt < 8; nt++) {
                int row = m0 + wm * 32 + mt * 16 + rr;
                int col = n0 + wn * 64 + nt * 8 + cc2;
                if (col < Nvalid) {
                    if (row < M)
                        *(float2*)(Cb + (long long)row * ldc + col) =
                            make_float2(acc[mt][nt][0], acc[mt][nt][1]);
                    if (row + 8 < M)
                        *(float2*)(Cb + (long long)(row + 8) * ldc + col) =
                            make_float2(acc[mt][nt][2], acc[mt][nt][3]);
                }
            }
        }
    } else {
        // fused Y epilogue (AX only: M=128, m0=0, Nvalid=DD, nsplit=1)
        #pragma unroll
        for (int mt = 0; mt < 2; mt++) {
            int rloc = wm * 32 + mt * 16 + rr;
            float sv0 = ys[batch * 128 + rloc];
            float sv1 = ys[batch * 128 + rloc + 8];
            long long yr0 = ((long long)(rloc >> 4) * LATROWS + batch * NL + (rloc & 15));
            int r2 = rloc + 8;
            long long yr1 = ((long long)(r2 >> 4) * LATROWS + batch * NL + (r2 & 15));
            #pragma unroll
            for (int nt = 0; nt < 8; nt++) {
                int col = n0 + wn * 64 + nt * 8 + cc2;
                float g0 = yg[col], g1 = yg[col + 1];
                *(float2*)(Cc + yr0 * DD + col) =
                    make_float2((acc[mt][nt][0] - sv0) * g0, (acc[mt][nt][1] - sv0) * g1);
                *(float2*)(Cc + yr1 * DD + col) =
                    make_float2((acc[mt][nt][2] - sv1) * g0, (acc[mt][nt][3] - sv1) * g1);
            }
        }
    }
}

// ---------------- generic split reduce + epilogue ----------------
__global__ void reduce_kernel(const float* __restrict__ parts, long long pstride, int nsplit,
                              float* __restrict__ out, long long n,
                              const float* __restrict__ addsrc, int add_mode,
                              const float* __restrict__ bias, int bias_period,
                              int do_gelu) {
    long long i = (long long)blockIdx.x * 256 + threadIdx.x;
    if (i >= n) return;
    float s = 0.f;
    for (int p = 0; p < nsplit; p++) s += parts[p * pstride + i];
    if (bias) s += bias[i % bias_period];
    if (do_gelu) s = 0.5f * s * (1.0f + erff(s * 0.70710678118654752f));
    if (add_mode == 1) s += addsrc[i];
    else if (add_mode == 2) {
        long long r = i >> 12;
        s += addsrc[((r & 15) << 12) + (i & 4095)];
    }
    out[i] = s;
}

// ---------------- qt_all (16 partials) ----------------
__global__ void qt_all_kernel(const float* __restrict__ qp, const float* __restrict__ wkv,
                              const float* __restrict__ g,
                              float* __restrict__ QTT, float* __restrict__ QG) {
    __shared__ float qs[NL * INNER];
    for (int i = threadIdx.x; i < NL * INNER; i += 256) {
        float s = 0.f;
        #pragma unroll
        for (int p = 0; p < 16; p++) s += qp[p * NL * INNER + i];
        qs[i] = s;
    }
    __syncthreads();
    int d = blockIdx.x * 32 + (threadIdx.x >> 3);
    int h = threadIdx.x & 7;
    const float* wrow = wkv + (long long)d * 1536 + h * DHH;
    float acc[NL];
    #pragma unroll
    for (int i = 0; i < NL; i++) acc[i] = 0.f;
    for (int dh = 0; dh < DHH; dh++) {
        float w = wrow[dh];
        #pragma unroll
        for (int i = 0; i < NL; i++) acc[i] = fmaf(qs[i * INNER + h * DHH + dh], w, acc[i]);
    }
    float gd = g[d];
    #pragma unroll
    for (int i = 0; i < NL; i++) {
        int ih = h * NL + i;
        QTT[(long long)d * 128 + ih] = acc[i];
        QG[(long long)d * 128 + ih] = acc[i] * gd;
    }
}

// ---------------- parallel u/v ----------------
__global__ void uv_part_kernel(const float* __restrict__ QTT, const float* __restrict__ g,
                               const float* __restrict__ b,
                               float* __restrict__ up, float* __restrict__ vp) {
    int ih = threadIdx.x;
    int c = blockIdx.x;
    float uu = 0.f, vv = 0.f;
    for (int d = c * 256; d < (c + 1) * 256; d++) {
        float t = QTT[(long long)d * 128 + ih];
        uu = fmaf(t, g[d], uu);
        vv = fmaf(t, b[d], vv);
    }
    up[c * 128 + ih] = uu;
    vp[c * 128 + ih] = vv;
}
__global__ void uv_comb_kernel(const float* __restrict__ up, const float* __restrict__ vp,
                               float* __restrict__ u, float* __restrict__ v) {
    int ih = threadIdx.x;
    float uu = 0.f, vv = 0.f;
    #pragma unroll
    for (int c = 0; c < 16; c++) { uu += up[c * 128 + ih]; vv += vp[c * 128 + ih]; }
    u[ih] = uu; v[ih] = vv;
}

// ---------------- parallel bv ----------------
__global__ void bv_part_kernel(const float* __restrict__ b, const float* __restrict__ wkv,
                               float* __restrict__ bvp) {
    int e = blockIdx.x * 128 + threadIdx.x;
    int c = blockIdx.y;
    float a = 0.f;
    for (int d = c * 256; d < (c + 1) * 256; d++)
        a = fmaf(b[d], wkv[(long long)d * 1536 + INNER + e], a);
    bvp[c * INNER + e] = a;
}
__global__ void bv_comb_kernel(const float* __restrict__ bvp, float* __restrict__ bv) {
    int e = blockIdx.x * 128 + threadIdx.x;
    float a = 0.f;
    #pragma unroll
    for (int c = 0; c < 16; c++) a += bvp[c * INNER + e];
    bv[e] = a;
}

// ---------------- attention softmax ----------------
__global__ void attn_kernel(const float* __restrict__ guid, const void* __restrict__ mask,
                            const float* __restrict__ S0, const float* __restrict__ mean,
                            const float* __restrict__ rstd,
                            const float* __restrict__ u, const float* __restrict__ v,
                            float* __restrict__ C, float* __restrict__ s_out) {
    extern __shared__ float sm[];
    float* sim = sm;
    float* rj  = sim + NL * NN;
    float* mj  = rj + NN;
    float* gu  = mj + NN;
    float* mk  = gu + NN;
    float* us  = mk + NN;
    float* vs  = us + NL;

    int bt = blockIdx.x >> 3;
    int h  = blockIdx.x & 7;
    int tid = threadIdx.x;
    int kind = g_mask_kind;

    for (int j = tid; j < NN; j += 256) {
        rj[j] = rstd[bt * NN + j];
        mj[j] = mean[bt * NN + j];
        gu[j] = guid[bt * NN + j];
        mk[j] = (kind == 1) ? (float)((const int*)mask)[bt * NN + j]
                            : (float)((const unsigned char*)mask)[bt * NN + j];
    }
    if (tid < NL) { us[tid] = u[h * NL + tid]; vs[tid] = v[h * NL + tid]; }
    __syncthreads();

    for (int idx = tid; idx < NL * NN; idx += 256) {
        int j = idx >> 4, i = idx & 15;
        float t = S0[((size_t)bt * NN + j) * 128 + h * NL + i];
        sim[i * NN + j] = ATTN_SCALE * (rj[j] * t - rj[j] * mj[j] * us[i] + vs[i]);
    }
    __syncthreads();

    int warp = tid >> 5, lane = tid & 31;
    for (int r = warp; r < NL; r += 8) {
        float* srow = sim + r * NN;
        float m0 = -FLT_MAX;
        for (int j = lane; j < NN; j += 32) m0 = fmaxf(m0, srow[j]);
        #pragma unroll
        for (int o = 16; o; o >>= 1) m0 = fmaxf(m0, __shfl_xor_sync(0xffffffffu, m0, o));

        float m1 = -FLT_MAX;
        for (int j = lane; j < NN; j += 32) {
            float s = srow[j] - m0;
            if (mk[j] != 0.f) s = -3.402823466e38f;
            s *= gu[j];
            srow[j] = s;
            m1 = fmaxf(m1, s);
        }
        #pragma unroll
        for (int o = 16; o; o >>= 1) m1 = fmaxf(m1, __shfl_xor_sync(0xffffffffu, m1, o));

        float sum = 0.f;
        for (int j = lane; j < NN; j += 32) {
            float e = expf(srow[j] - m1);
            srow[j] = e;
            sum += e;
        }
        #pragma unroll
        for (int o = 16; o; o >>= 1) sum += __shfl_xor_sync(0xffffffffu, sum, o);
        float inv = 1.f / sum;

        float sacc = 0.f;
        float* crow = C + ((size_t)bt * 128 + h * NL + r) * NN;
        for (int j = lane; j < NN; j += 32) {
            float a = srow[j] * inv;
            float c = a * rj[j];
            crow[j] = c;
            sacc = fmaf(c, mj[j], sacc);
        }
        #pragma unroll
        for (int o = 16; o; o >>= 1) sacc += __shfl_xor_sync(0xffffffffu, sacc, o);
        if (lane == 0) s_out[bt * 128 + h * NL + r] = sacc;
    }
}

// ---------------- launch ----------------
extern "C" void kernel_launch(void* const* d_in, const int* in_sizes, int n_in,
                              void* d_out, int out_size) {
    const float* x       = (const float*)d_in[0];
    const float* guid    = (const float*)d_in[1];
    const void*  mask    = d_in[2];
    const float* latents = (const float*)d_in[3];
    const float* nm_g    = (const float*)d_in[4];
    const float* nm_b    = (const float*)d_in[5];
    const float* nl_g    = (const float*)d_in[6];
    const float* nl_b    = (const float*)d_in[7];
    const float* wq      = (const float*)d_in[8];
    const float* wkv     = (const float*)d_in[9];
    const float* wout    = (const float*)d_in[10];
    const float* ff_g    = (const float*)d_in[11];
    const float* ff_b    = (const float*)d_in[12];
    const float* w1      = (const float*)d_in[13];
    const float* w2      = (const float*)d_in[14];
    const float* fn_g    = (const float*)d_in[15];
    const float* fn_b    = (const float*)d_in[16];
    float* out = (float*)d_out;

    float *p_mean, *p_rstd, *p_ql, *p_qp, *p_QTT, *p_QG, *p_u, *p_v, *p_bv;
    float *p_up, *p_vp, *p_bvp;
    float *p_S0, *p_C, *p_s, *p_Y, *p_Vp, *p_attnv, *p_woutp;
    float *p_lat1, *p_ffln, *p_ff1p, *p_h1, *p_ff2p, *p_lat2;
    cudaGetSymbolAddress((void**)&p_mean, g_mean);
    cudaGetSymbolAddress((void**)&p_rstd, g_rstd);
    cudaGetSymbolAddress((void**)&p_ql, g_ql);
    cudaGetSymbolAddress((void**)&p_qp, g_qp);
    cudaGetSymbolAddress((void**)&p_QTT, g_QTT);
    cudaGetSymbolAddress((void**)&p_QG, g_QG);
    cudaGetSymbolAddress((void**)&p_u, g_u);
    cudaGetSymbolAddress((void**)&p_v, g_v);
    cudaGetSymbolAddress((void**)&p_bv, g_bv);
    cudaGetSymbolAddress((void**)&p_up, g_up);
    cudaGetSymbolAddress((void**)&p_vp, g_vp);
    cudaGetSymbolAddress((void**)&p_bvp, g_bvp);
    cudaGetSymbolAddress((void**)&p_S0, g_S0);
    cudaGetSymbolAddress((void**)&p_C, g_C);
    cudaGetSymbolAddress((void**)&p_s, g_s);
    cudaGetSymbolAddress((void**)&p_Y, g_Y);
    cudaGetSymbolAddress((void**)&p_Vp, g_Vp);
    cudaGetSymbolAddress((void**)&p_attnv, g_attnv);
    cudaGetSymbolAddress((void**)&p_woutp, g_woutp);
    cudaGetSymbolAddress((void**)&p_lat1, g_lat1);
    cudaGetSymbolAddress((void**)&p_ffln, g_ffln);
    cudaGetSymbolAddress((void**)&p_ff1p, g_ff1p);
    cudaGetSymbolAddress((void**)&p_h1, g_h1);
    cudaGetSymbolAddress((void**)&p_ff2p, g_ff2p);
    cudaGetSymbolAddress((void**)&p_lat2, g_lat2);

    cudaFuncSetAttribute(hmma3, cudaFuncAttributeMaxDynamicSharedMemorySize, HSMEM3);
    cudaFuncSetAttribute(hmma2, cudaFuncAttributeMaxDynamicSharedMemorySize, HSMEM2);

    // #1 ql = LN(latents)
    ln_rows_kernel<<<NL, 256>>>(latents, p_ql, nl_g, nl_b);
    // #2 qp = ql @ wq partials (split-K 16, bf16 3-term: score path precompute)
    hmma3<<<dim3(6, 1, 16), 256, HSMEM3>>>(p_ql, DD, 0, wq, INNER, 0,
                                           p_qp, INNER, 0, NL * INNER,
                                           NL, INNER, DD, 16);
    // #3 qt_all
    qt_all_kernel<<<DD / 32, 256>>>(p_qp, wkv, nm_g, p_QTT, p_QG);

    // #4 S0 = x @ QG (fp16 2-term) + fused x row stats
    hmma2<<<dim3(1, XROWS / 128, 1), 256, HSMEM2>>>(
        x, DD, 0, p_QG, 128, 0,
        p_S0, 128, 0, 0, XROWS, 128, DD, 1,
        nullptr, nullptr, p_mean, p_rstd);

    // u/v (parallel), bv (parallel), mask-kind
    uv_part_kernel<<<16, 128>>>(p_QTT, nm_g, nm_b, p_up, p_vp);
    uv_comb_kernel<<<1, 128>>>(p_up, p_vp, p_u, p_v);
    bv_part_kernel<<<dim3(INNER / 128, 16), 128>>>(nm_b, wkv, p_bvp);
    bv_comb_kernel<<<INNER / 128, 128>>>(p_bvp, p_bv);
    detect_mask_kernel<<<1, 256>>>((const unsigned int*)mask);

    // softmax -> C, s
    {
        int smemb = (NL * NN + 4 * NN + 2 * NL) * (int)sizeof(float);
        cudaFuncSetAttribute(attn_kernel, cudaFuncAttributeMaxDynamicSharedMemorySize, smemb);
        attn_kernel<<<BT * HH, 256, smemb>>>(guid, mask, p_S0, p_mean, p_rstd,
                                             p_u, p_v, p_C, p_s);
    }

    // AX[bt] = C[bt] @ x[bt] with fused Y epilogue
    hmma2<<<dim3(DD / 128, 1, BT), 256, HSMEM2>>>(
        p_C, NN, (long long)128 * NN, x, DD, (long long)NN * DD,
        p_Y, DD, 0, 0, 128, DD, NN, 1, nm_g, p_s, nullptr, nullptr);

    // attnV (split-K 16)
    hmma2<<<dim3(1, 2, HH * 16), 256, HSMEM2>>>(
        p_Y, DD, (long long)LATROWS * DD, wkv + INNER, 1536, 96,
        p_Vp, INNER, 96, (long long)LATROWS * INNER, LATROWS, 96, DD, 16,
        nullptr, nullptr, nullptr, nullptr);
    reduce_kernel<<<(LATROWS * INNER + 255) / 256, 256>>>(
        p_Vp, (long long)LATROWS * INNER, 16, p_attnv, LATROWS * INNER,
        nullptr, 0, p_bv, INNER, 0);

    // lat1 = attnv @ wout + latents (split-K 4)
    hmma2<<<dim3(DD / 128, 2, 4), 256, HSMEM2>>>(
        p_attnv, INNER, 0, wout, DD, 0,
        p_woutp, DD, 0, (long long)LATROWS * DD, LATROWS, DD, INNER, 4,
        nullptr, nullptr, nullptr, nullptr);
    reduce_kernel<<<(LATROWS * DD + 255) / 256, 256>>>(
        p_woutp, (long long)LATROWS * DD, 4, p_lat1, LATROWS * DD,
        latents, 2, nullptr, 1, 0);

    // FF
    ln_rows_kernel<<<LATROWS, 256>>>(p_lat1, p_ffln, ff_g, ff_b);
    hmma2<<<dim3(FF / 128, 2, 2), 256, HSMEM2>>>(
        p_ffln, DD, 0, w1, FF, 0,
        p_ff1p, FF, 0, (long long)LATROWS * FF, LATROWS, FF, DD, 2,
        nullptr, nullptr, nullptr, nullptr);
    reduce_kernel<<<((long long)LATROWS * FF + 255) / 256, 256>>>(
        p_ff1p, (long long)LATROWS * FF, 2, p_h1, (long long)LATROWS * FF,
        nullptr, 0, nullptr, 1, 1);
    hmma2<<<dim3(DD / 128, 2, 4), 256, HSMEM2>>>(
        p_h1, FF, 0, w2, DD, 0,
        p_ff2p, DD, 0, (long long)LATROWS * DD, LATROWS, DD, FF, 4,
        nullptr, nullptr, nullptr, nullptr);
    reduce_kernel<<<(LATROWS * DD + 255) / 256, 256>>>(
        p_ff2p, (long long)LATROWS * DD, 4, p_lat2, LATROWS * DD,
        p_lat1, 1, nullptr, 1, 0);

    // final LN
    ln_rows_kernel<<<LATROWS, 256>>>(p_lat2, out, fn_g, fn_b);
}